// round 1
// baseline (speedup 1.0000x reference)
#include <cuda_runtime.h>
#include <math.h>

// Problem constants (fixed shapes from setup_inputs)
#define BATCH 8
#define CDIM 512
#define TDIM 1024
#define HEADS_ 8
#define EPS_ 1e-5f
#define RES_SCALE_ 0.7071067811865476f
#define QK_SCALE 0.35355339059327373f   // 64^-0.25 = 2^-1.5

// Scratch (static device allocations; no runtime alloc)
__device__ float g_xn  [BATCH * CDIM * TDIM];          // 16 MB
__device__ float g_qkv [BATCH * 3 * CDIM * TDIM];      // 48 MB
__device__ float g_attn[BATCH * CDIM * TDIM];          // 16 MB
__device__ float g_h   [BATCH * CDIM * TDIM];          // 16 MB

// ---------------------------------------------------------------------------
// Block-wide (256 threads) sum + sumsq reduction
// ---------------------------------------------------------------------------
__device__ __forceinline__ void block_reduce2(float& s, float& s2, float* sh)
{
    #pragma unroll
    for (int o = 16; o > 0; o >>= 1) {
        s  += __shfl_down_sync(0xffffffffu, s,  o);
        s2 += __shfl_down_sync(0xffffffffu, s2, o);
    }
    int warp = threadIdx.x >> 5, lane = threadIdx.x & 31;
    if (lane == 0) { sh[warp] = s; sh[8 + warp] = s2; }
    __syncthreads();
    if (threadIdx.x < 32) {
        s  = (lane < 8) ? sh[lane]     : 0.f;
        s2 = (lane < 8) ? sh[8 + lane] : 0.f;
        #pragma unroll
        for (int o = 4; o > 0; o >>= 1) {
            s  += __shfl_down_sync(0xffffffffu, s,  o);
            s2 += __shfl_down_sync(0xffffffffu, s2, o);
        }
        if (lane == 0) { sh[0] = s; sh[1] = s2; }
    }
    __syncthreads();
    s = sh[0]; s2 = sh[1];
}

// ---------------------------------------------------------------------------
// GroupNorm #1 (affine): x -> g_xn.  One block per (batch, group).
// Group = 16 channels x 1024 = 16384 floats; held in registers (16 float4/thr).
// ---------------------------------------------------------------------------
__global__ __launch_bounds__(256) void gn1_kernel(const float* __restrict__ x,
                                                  const float* __restrict__ w,
                                                  const float* __restrict__ bia)
{
    __shared__ float sh[16];
    int blk = blockIdx.x;
    int b = blk >> 5, g = blk & 31;
    size_t off = ((size_t)b * CDIM + (size_t)g * 16) * TDIM;
    const float4* xp = (const float4*)(x + off);
    int tid = threadIdx.x;

    float4 v[16];
    float s = 0.f, s2 = 0.f;
    #pragma unroll
    for (int j = 0; j < 16; j++) {
        float4 a = xp[j * 256 + tid];
        v[j] = a;
        s  += a.x + a.y + a.z + a.w;
        s2 += a.x*a.x + a.y*a.y + a.z*a.z + a.w*a.w;
    }
    block_reduce2(s, s2, sh);
    float mean = s * (1.f / 16384.f);
    float var  = s2 * (1.f / 16384.f) - mean * mean;
    float rstd = rsqrtf(var + EPS_);

    float4* op = (float4*)(g_xn + off);
    #pragma unroll
    for (int j = 0; j < 16; j++) {
        // float4 index j*256+tid -> channel-within-group = j (1024 fl = 256 f4/ch)
        int ch = g * 16 + j;
        float sc  = w[ch] * rstd;
        float shf = bia[ch] - mean * sc;
        float4 a = v[j], o;
        o.x = a.x * sc + shf; o.y = a.y * sc + shf;
        o.z = a.z * sc + shf; o.w = a.w * sc + shf;
        op[j * 256 + tid] = o;
    }
}

// ---------------------------------------------------------------------------
// SGEMM: C[z][m][n] = A[m][k] * B[z][k][n] + bias[m], N = 1024 fixed.
// 128x128 block tile, BK=16, 256 threads, 8x8 microtile.
// MODE 0: B = g_xn,   C = g_qkv (q/k rows scaled by 64^-0.25 after bias)
// MODE 1: B = g_attn, C = g_h
// ---------------------------------------------------------------------------
template <int MODE>
__global__ __launch_bounds__(256) void sgemm_kernel(const float* __restrict__ A,
                                                    const float* __restrict__ bias,
                                                    int M, int K)
{
    const int N = TDIM;
    const float* B = (MODE == 0 ? g_xn   : g_attn) + (size_t)blockIdx.z * CDIM * TDIM;
    float*       C = (MODE == 0 ? g_qkv  : g_h)
                   + (size_t)blockIdx.z * (MODE == 0 ? 3 * CDIM : CDIM) * TDIM;

    __shared__ float As[16][132];
    __shared__ float Bs[16][128];

    int tid = threadIdx.x;
    int tm = tid >> 4, tn = tid & 15;
    int row0 = blockIdx.y * 128;
    int col0 = blockIdx.x * 128;

    int aRow = tid >> 2;            // 0..63 (+64)
    int aK   = (tid & 3) << 2;      // 0,4,8,12
    int bK   = tid >> 5;            // 0..7 (+8)
    int bCol = (tid & 31) << 2;     // 0..124

    float acc[8][8];
    #pragma unroll
    for (int i = 0; i < 8; i++)
        #pragma unroll
        for (int j = 0; j < 8; j++) acc[i][j] = 0.f;

    for (int k0 = 0; k0 < K; k0 += 16) {
        #pragma unroll
        for (int r = 0; r < 2; r++) {
            int row = aRow + r * 64;
            float4 a4 = *(const float4*)(A + (size_t)(row0 + row) * K + k0 + aK);
            As[aK + 0][row] = a4.x; As[aK + 1][row] = a4.y;
            As[aK + 2][row] = a4.z; As[aK + 3][row] = a4.w;
        }
        #pragma unroll
        for (int r = 0; r < 2; r++) {
            int kk = bK + r * 8;
            *(float4*)&Bs[kk][bCol] =
                *(const float4*)(B + (size_t)(k0 + kk) * N + col0 + bCol);
        }
        __syncthreads();
        #pragma unroll
        for (int kk = 0; kk < 16; kk++) {
            float ra[8], rb[8];
            *(float4*)(ra)     = *(const float4*)&As[kk][tm * 8];
            *(float4*)(ra + 4) = *(const float4*)&As[kk][tm * 8 + 4];
            *(float4*)(rb)     = *(const float4*)&Bs[kk][tn * 8];
            *(float4*)(rb + 4) = *(const float4*)&Bs[kk][tn * 8 + 4];
            #pragma unroll
            for (int i = 0; i < 8; i++)
                #pragma unroll
                for (int j = 0; j < 8; j++)
                    acc[i][j] += ra[i] * rb[j];
        }
        __syncthreads();
    }

    #pragma unroll
    for (int i = 0; i < 8; i++) {
        int m = row0 + tm * 8 + i;
        float bv = bias[m];
        float scale = 1.f;
        if (MODE == 0) {
            int which = (m % 192) / 64;   // 0=q 1=k 2=v within head
            if (which < 2) scale = QK_SCALE;
        }
        float o[8];
        #pragma unroll
        for (int j = 0; j < 8; j++) o[j] = (acc[i][j] + bv) * scale;
        float* cp = C + (size_t)m * N + col0 + tn * 8;
        *(float4*)cp       = *(float4*)(o);
        *(float4*)(cp + 4) = *(float4*)(o + 4);
    }
}

// ---------------------------------------------------------------------------
// Flash attention, fp32, one thread per query column (natural [c,t] layout).
// grid = (8 q-tiles, 64 batch-heads), 128 threads.
// q/k already scaled by 64^-0.25 in the QKV epilogue.
// ---------------------------------------------------------------------------
__global__ __launch_bounds__(128) void attn_kernel()
{
    __shared__ float Ks[64][68];   // [c][s], padded, float4-aligned rows
    __shared__ float Vs[64][68];

    int bh = blockIdx.y;
    int b = bh >> 3, head = bh & 7;
    int tq = blockIdx.x * 128 + threadIdx.x;

    const float* base = g_qkv + ((size_t)b * 1536 + head * 192) * TDIM;
    const float* qp = base;
    const float* kp = base + (size_t)64 * TDIM;
    const float* vp = base + (size_t)128 * TDIM;

    float q[64], acc[64];
    #pragma unroll
    for (int c = 0; c < 64; c++) {
        q[c] = qp[(size_t)c * TDIM + tq];
        acc[c] = 0.f;
    }

    float mrun = -1e30f, lrun = 0.f;

    for (int s0 = 0; s0 < TDIM; s0 += 64) {
        __syncthreads();
        #pragma unroll
        for (int j = 0; j < 8; j++) {
            int idx = j * 128 + threadIdx.x;       // float4 index in 64x64 tile
            int c = idx >> 4, s4 = (idx & 15) << 2;
            *(float4*)&Ks[c][s4] = *(const float4*)(kp + (size_t)c * TDIM + s0 + s4);
            *(float4*)&Vs[c][s4] = *(const float4*)(vp + (size_t)c * TDIM + s0 + s4);
        }
        __syncthreads();

        #pragma unroll 1
        for (int u = 0; u < 64; u += 16) {
            float sc[16];
            #pragma unroll
            for (int j = 0; j < 16; j++) sc[j] = 0.f;

            // scores: sc[s] += q[c] * K[c][s]   (float4 broadcast smem reads)
            #pragma unroll 16
            for (int c = 0; c < 64; c++) {
                float qc = q[c];
                #pragma unroll
                for (int j = 0; j < 4; j++) {
                    float4 k4 = *(const float4*)&Ks[c][u + j * 4];
                    sc[4*j+0] += qc * k4.x; sc[4*j+1] += qc * k4.y;
                    sc[4*j+2] += qc * k4.z; sc[4*j+3] += qc * k4.w;
                }
            }

            float cm = sc[0];
            #pragma unroll
            for (int j = 1; j < 16; j++) cm = fmaxf(cm, sc[j]);
            if (cm > mrun) {
                float corr = __expf(mrun - cm);
                lrun *= corr;
                #pragma unroll
                for (int c = 0; c < 64; c++) acc[c] *= corr;
                mrun = cm;
            }
            float psum = 0.f;
            #pragma unroll
            for (int j = 0; j < 16; j++) { sc[j] = __expf(sc[j] - mrun); psum += sc[j]; }
            lrun += psum;

            // acc[c] += sum_s p[s] * V[c][s]
            #pragma unroll 16
            for (int c = 0; c < 64; c++) {
                float a = acc[c];
                #pragma unroll
                for (int j = 0; j < 4; j++) {
                    float4 v4 = *(const float4*)&Vs[c][u + j * 4];
                    a += sc[4*j+0]*v4.x + sc[4*j+1]*v4.y
                       + sc[4*j+2]*v4.z + sc[4*j+3]*v4.w;
                }
                acc[c] = a;
            }
        }
    }

    float inv = 1.f / lrun;
    float* op = g_attn + ((size_t)b * CDIM + head * 64) * TDIM + tq;
    #pragma unroll
    for (int c = 0; c < 64; c++) op[(size_t)c * TDIM] = acc[c] * inv;
}

// ---------------------------------------------------------------------------
// GroupNorm #2 (no affine) over y = RES_SCALE*xn + h  -> d_out
// ---------------------------------------------------------------------------
__global__ __launch_bounds__(256) void gn2_kernel(float* __restrict__ out)
{
    __shared__ float sh[16];
    int blk = blockIdx.x;
    int b = blk >> 5, g = blk & 31;
    size_t off = ((size_t)b * CDIM + (size_t)g * 16) * TDIM;
    const float4* xp = (const float4*)(g_xn + off);
    const float4* hp = (const float4*)(g_h + off);
    int tid = threadIdx.x;

    float4 v[16];
    float s = 0.f, s2 = 0.f;
    #pragma unroll
    for (int j = 0; j < 16; j++) {
        float4 a = xp[j * 256 + tid];
        float4 c = hp[j * 256 + tid];
        float4 y;
        y.x = RES_SCALE_ * a.x + c.x;
        y.y = RES_SCALE_ * a.y + c.y;
        y.z = RES_SCALE_ * a.z + c.z;
        y.w = RES_SCALE_ * a.w + c.w;
        v[j] = y;
        s  += y.x + y.y + y.z + y.w;
        s2 += y.x*y.x + y.y*y.y + y.z*y.z + y.w*y.w;
    }
    block_reduce2(s, s2, sh);
    float mean = s * (1.f / 16384.f);
    float var  = s2 * (1.f / 16384.f) - mean * mean;
    float rstd = rsqrtf(var + EPS_);

    float4* op = (float4*)(out + off);
    #pragma unroll
    for (int j = 0; j < 16; j++) {
        float4 y = v[j], o;
        o.x = (y.x - mean) * rstd; o.y = (y.y - mean) * rstd;
        o.z = (y.z - mean) * rstd; o.w = (y.w - mean) * rstd;
        op[j * 256 + tid] = o;
    }
}

// ---------------------------------------------------------------------------
extern "C" void kernel_launch(void* const* d_in, const int* in_sizes, int n_in,
                              void* d_out, int out_size)
{
    const float* x      = (const float*)d_in[0];
    const float* gn_w   = (const float*)d_in[1];
    const float* gn_b   = (const float*)d_in[2];
    const float* qkv_w  = (const float*)d_in[3];
    const float* qkv_b  = (const float*)d_in[4];
    const float* proj_w = (const float*)d_in[5];
    const float* proj_b = (const float*)d_in[6];
    float* out = (float*)d_out;

    // 1) GroupNorm(affine) -> g_xn
    gn1_kernel<<<BATCH * 32, 256>>>(x, gn_w, gn_b);

    // 2) QKV GEMM: [1536,512] x [8][512,1024] -> g_qkv (q,k pre-scaled)
    sgemm_kernel<0><<<dim3(TDIM / 128, 1536 / 128, BATCH), 256>>>(qkv_w, qkv_b,
                                                                  1536, CDIM);

    // 3) Flash attention per head -> g_attn
    attn_kernel<<<dim3(TDIM / 128, BATCH * HEADS_), 128>>>();

    // 4) proj GEMM: [512,512] x [8][512,1024] -> g_h
    sgemm_kernel<1><<<dim3(TDIM / 128, CDIM / 128, BATCH), 256>>>(proj_w, proj_b,
                                                                  CDIM, CDIM);

    // 5) residual + GroupNorm(no affine) -> out
    gn2_kernel<<<BATCH * 32, 256>>>(out);
}

// round 3
// speedup vs baseline: 3.3683x; 3.3683x over previous
#include <cuda_runtime.h>
#include <cstdint>
#include <math.h>

// Problem constants
#define BATCH 8
#define CDIM 512
#define TDIM 1024
#define HEADS_ 8
#define EPS_ 1e-5f
#define RES_SCALE_ 0.7071067811865476f
#define QK_SCALE 0.35355339059327373f   // 64^-0.25

// Scratch
__device__ float g_xn   [BATCH * CDIM * TDIM];   // normalized x, [c,t]
__device__ float g_xnt  [BATCH * TDIM * CDIM];   // normalized x, [t,c] (GEMM B)
__device__ float g_qkv  [BATCH * 3 * CDIM * TDIM];
__device__ float g_attnt[BATCH * TDIM * CDIM];   // attention out, [t,c]
__device__ float g_h    [BATCH * CDIM * TDIM];

// ===========================================================================
// mma.sync tf32 helpers (sm_80+ path; tcgen05 unavailable on compute_103)
// ===========================================================================
__device__ __forceinline__ uint32_t f2tf(float f) {
    uint32_t u;
    asm("cvt.rna.tf32.f32 %0, %1;" : "=r"(u) : "f"(f));
    return u;
}
__device__ __forceinline__ void mma_tf32(float* d, const uint32_t* a,
                                         const uint32_t* b) {
    asm volatile(
        "mma.sync.aligned.m16n8k8.row.col.f32.tf32.tf32.f32 "
        "{%0,%1,%2,%3}, {%4,%5,%6,%7}, {%8,%9}, {%0,%1,%2,%3};"
        : "+f"(d[0]), "+f"(d[1]), "+f"(d[2]), "+f"(d[3])
        : "r"(a[0]), "r"(a[1]), "r"(a[2]), "r"(a[3]), "r"(b[0]), "r"(b[1]));
}

// ===========================================================================
// Block-wide (256 threads) sum + sumsq reduction
// ===========================================================================
__device__ __forceinline__ void block_reduce2(float& s, float& s2, float* sh)
{
    #pragma unroll
    for (int o = 16; o > 0; o >>= 1) {
        s  += __shfl_down_sync(0xffffffffu, s,  o);
        s2 += __shfl_down_sync(0xffffffffu, s2, o);
    }
    int warp = threadIdx.x >> 5, lane = threadIdx.x & 31;
    if (lane == 0) { sh[warp] = s; sh[8 + warp] = s2; }
    __syncthreads();
    if (threadIdx.x < 32) {
        s  = (lane < 8) ? sh[lane]     : 0.f;
        s2 = (lane < 8) ? sh[8 + lane] : 0.f;
        #pragma unroll
        for (int o = 4; o > 0; o >>= 1) {
            s  += __shfl_down_sync(0xffffffffu, s,  o);
            s2 += __shfl_down_sync(0xffffffffu, s2, o);
        }
        if (lane == 0) { sh[0] = s; sh[1] = s2; }
    }
    __syncthreads();
    s = sh[0]; s2 = sh[1];
}

// ===========================================================================
// GroupNorm #1 (affine): x -> g_xn [c,t] AND g_xnt [t,c]
// ===========================================================================
__global__ __launch_bounds__(256) void gn1_kernel(const float* __restrict__ x,
                                                  const float* __restrict__ w,
                                                  const float* __restrict__ bia)
{
    __shared__ float sh[16];
    int blk = blockIdx.x;
    int b = blk >> 5, g = blk & 31;
    size_t off = ((size_t)b * CDIM + (size_t)g * 16) * TDIM;
    const float4* xp = (const float4*)(x + off);
    int tid = threadIdx.x;

    float4 v[16];
    float s = 0.f, s2 = 0.f;
    #pragma unroll
    for (int j = 0; j < 16; j++) {
        float4 a = xp[j * 256 + tid];
        v[j] = a;
        s  += a.x + a.y + a.z + a.w;
        s2 += a.x*a.x + a.y*a.y + a.z*a.z + a.w*a.w;
    }
    block_reduce2(s, s2, sh);
    float mean = s * (1.f / 16384.f);
    float var  = s2 * (1.f / 16384.f) - mean * mean;
    float rstd = rsqrtf(var + EPS_);

    float scl[16], shf[16];
    #pragma unroll
    for (int j = 0; j < 16; j++) {
        int ch = g * 16 + j;
        scl[j] = w[ch] * rstd;
        shf[j] = bia[ch] - mean * scl[j];
    }

    float4* op = (float4*)(g_xn + off);
    #pragma unroll
    for (int j = 0; j < 16; j++) {
        float4 a = v[j], o;
        o.x = a.x * scl[j] + shf[j]; o.y = a.y * scl[j] + shf[j];
        o.z = a.z * scl[j] + shf[j]; o.w = a.w * scl[j] + shf[j];
        v[j] = o;
        op[j * 256 + tid] = o;
    }

    float* xt = g_xnt + ((size_t)b * TDIM + (size_t)tid * 4) * CDIM + g * 16;
    #pragma unroll
    for (int u = 0; u < 4; u++) {
        float tmp[16];
        #pragma unroll
        for (int j = 0; j < 16; j++) tmp[j] = ((const float*)&v[j])[u];
        float* r = xt + (size_t)u * CDIM;
        *(float4*)(r + 0)  = *(float4*)(tmp + 0);
        *(float4*)(r + 4)  = *(float4*)(tmp + 4);
        *(float4*)(r + 8)  = *(float4*)(tmp + 8);
        *(float4*)(r + 12) = *(float4*)(tmp + 12);
    }
}

// ===========================================================================
// tf32 mma GEMM: C[bz][m][t] = W[m][k] * Bt[bz][t][k] + bias[m]
// 128x128 tile, KC=32, 8 warps (4m x 2n), warp tile 32x64.
// MODE 0: Bt=g_xnt,   C=g_qkv (M=1536; q,k rows scaled)
// MODE 1: Bt=g_attnt, C=g_h   (M=512)
// ===========================================================================
#define KC 32
#define ASTR 36   // smem row stride (36 % 32 == 4 -> conflict-free frags)

template <int MODE>
__global__ __launch_bounds__(256) void mma_gemm(const float* __restrict__ A,
                                                const float* __restrict__ bias)
{
    __shared__ uint32_t As[128 * ASTR];
    __shared__ uint32_t Bs[128 * ASTR];

    const int tid  = threadIdx.x;
    const int lane = tid & 31;
    const int wrp  = tid >> 5;
    const int g    = lane >> 2, tig = lane & 3;
    const int m0w  = (wrp & 3) * 32;
    const int n0w  = (wrp >> 2) * 64;

    const int row0 = blockIdx.y * 128;
    const int col0 = blockIdx.x * 128;
    const float* Bt = (MODE == 0 ? g_xnt : g_attnt) + (size_t)blockIdx.z * TDIM * CDIM;
    float*       C  = (MODE == 0 ? g_qkv : g_h)
                    + (size_t)blockIdx.z * (MODE == 0 ? 3 * CDIM : CDIM) * TDIM;

    const float* Ab = A  + (size_t)row0 * CDIM;
    const float* Bb = Bt + (size_t)col0 * CDIM;

    float acc[2][8][4];
    #pragma unroll
    for (int mt = 0; mt < 2; mt++)
        #pragma unroll
        for (int nt = 0; nt < 8; nt++)
            #pragma unroll
            for (int j = 0; j < 4; j++) acc[mt][nt][j] = 0.f;

    float4 aR[4], bR[4];
    auto ldg = [&](int k0) {
        #pragma unroll
        for (int s = 0; s < 4; s++) {
            int i = tid + s * 256;
            aR[s] = *(const float4*)(Ab + (size_t)(i >> 3) * CDIM + k0 + (i & 7) * 4);
            bR[s] = *(const float4*)(Bb + (size_t)(i >> 3) * CDIM + k0 + (i & 7) * 4);
        }
    };
    auto sts = [&]() {
        #pragma unroll
        for (int s = 0; s < 4; s++) {
            int i = tid + s * 256;
            int base = (i >> 3) * ASTR + (i & 7) * 4;
            As[base + 0] = f2tf(aR[s].x); As[base + 1] = f2tf(aR[s].y);
            As[base + 2] = f2tf(aR[s].z); As[base + 3] = f2tf(aR[s].w);
            Bs[base + 0] = f2tf(bR[s].x); Bs[base + 1] = f2tf(bR[s].y);
            Bs[base + 2] = f2tf(bR[s].z); Bs[base + 3] = f2tf(bR[s].w);
        }
    };

    ldg(0);
    #pragma unroll 1
    for (int it = 0; it < CDIM / KC; it++) {
        __syncthreads();
        sts();
        __syncthreads();
        if (it < CDIM / KC - 1) ldg((it + 1) * KC);

        #pragma unroll
        for (int ks = 0; ks < 4; ks++) {
            uint32_t aF[2][4];
            #pragma unroll
            for (int mt = 0; mt < 2; mt++) {
                int r = m0w + mt * 16;
                aF[mt][0] = As[(r + g)     * ASTR + ks * 8 + tig];
                aF[mt][1] = As[(r + g + 8) * ASTR + ks * 8 + tig];
                aF[mt][2] = As[(r + g)     * ASTR + ks * 8 + tig + 4];
                aF[mt][3] = As[(r + g + 8) * ASTR + ks * 8 + tig + 4];
            }
            #pragma unroll
            for (int nt = 0; nt < 8; nt++) {
                uint32_t bF[2];
                int n = n0w + nt * 8 + g;
                bF[0] = Bs[n * ASTR + ks * 8 + tig];
                bF[1] = Bs[n * ASTR + ks * 8 + tig + 4];
                mma_tf32(acc[0][nt], aF[0], bF);
                mma_tf32(acc[1][nt], aF[1], bF);
            }
        }
    }

    // Epilogue
    #pragma unroll
    for (int mt = 0; mt < 2; mt++) {
        #pragma unroll
        for (int rr = 0; rr < 2; rr++) {
            int m = row0 + m0w + mt * 16 + g + rr * 8;
            float bv = bias[m];
            float scale = 1.f;
            if (MODE == 0) { if (((m % 192) >> 6) < 2) scale = QK_SCALE; }
            float* crow = C + (size_t)m * TDIM + col0 + n0w;
            #pragma unroll
            for (int nt = 0; nt < 8; nt++) {
                float2 o;
                o.x = (acc[mt][nt][rr * 2 + 0] + bv) * scale;
                o.y = (acc[mt][nt][rr * 2 + 1] + bv) * scale;
                *(float2*)(crow + nt * 8 + 2 * tig) = o;
            }
        }
    }
}

// ===========================================================================
// Flash attention with tf32 mma. Block = (b,head) x 128 queries, 256 thr.
// Warp w owns 16 queries. qkv layout [m][t]; q,k pre-scaled by 64^-0.25.
// Output: g_attnt[b][t][c].
// smem: Ks[64][76], Vs[64][76] (tf32), Ps[128][68] (tf32)
// ===========================================================================
#define KSTR 76   // 76 % 32 == 12: conflict-free for both (12*tig+g) and (12*g+tig)
#define PSTR 68   // 68 % 32 == 4:  conflict-free A-frag reads
#define ATTN_SMEM ((64 * KSTR * 2 + 128 * PSTR) * 4)

__global__ __launch_bounds__(256) void attn_mma_kernel()
{
    extern __shared__ uint32_t dyn[];
    uint32_t* Ks = dyn;
    uint32_t* Vs = dyn + 64 * KSTR;
    uint32_t* Ps = dyn + 128 * KSTR;

    const int tid  = threadIdx.x;
    const int lane = tid & 31;
    const int wrp  = tid >> 5;
    const int g    = lane >> 2, tig = lane & 3;
    const int ql   = wrp * 16;            // block-local query row base

    const int bh = blockIdx.y;
    const int b = bh >> 3, head = bh & 7;
    const int q0 = blockIdx.x * 128;

    const float* base = g_qkv + ((size_t)b * 1536 + head * 192) * TDIM;
    const float* qp = base;
    const float* kp = base + (size_t)64 * TDIM;
    const float* vp = base + (size_t)128 * TDIM;

    // Q fragments, register-resident: A = Q^T[tq][c]
    uint32_t aQ[8][4];
    #pragma unroll
    for (int kk = 0; kk < 8; kk++) {
        int c0 = kk * 8;
        aQ[kk][0] = f2tf(qp[(size_t)(c0 + tig)     * TDIM + q0 + ql + g]);
        aQ[kk][1] = f2tf(qp[(size_t)(c0 + tig)     * TDIM + q0 + ql + g + 8]);
        aQ[kk][2] = f2tf(qp[(size_t)(c0 + tig + 4) * TDIM + q0 + ql + g]);
        aQ[kk][3] = f2tf(qp[(size_t)(c0 + tig + 4) * TDIM + q0 + ql + g + 8]);
    }

    float oacc[8][4];
    #pragma unroll
    for (int ct = 0; ct < 8; ct++)
        #pragma unroll
        for (int j = 0; j < 4; j++) oacc[ct][j] = 0.f;
    float m0 = -1e30f, m1 = -1e30f, l0 = 0.f, l1 = 0.f;

    #pragma unroll 1
    for (int kt = 0; kt < 16; kt++) {
        const int s0 = kt * 64;
        __syncthreads();   // previous iter's smem reads done
        // load K/V tiles (64c x 64s), convert to tf32
        #pragma unroll
        for (int s = 0; s < 4; s++) {
            int idx = tid + s * 256;
            int c = idx >> 4, s4 = (idx & 15) << 2;
            float4 k4 = *(const float4*)(kp + (size_t)c * TDIM + s0 + s4);
            float4 v4 = *(const float4*)(vp + (size_t)c * TDIM + s0 + s4);
            int o = c * KSTR + s4;
            Ks[o+0] = f2tf(k4.x); Ks[o+1] = f2tf(k4.y);
            Ks[o+2] = f2tf(k4.z); Ks[o+3] = f2tf(k4.w);
            Vs[o+0] = f2tf(v4.x); Vs[o+1] = f2tf(v4.y);
            Vs[o+2] = f2tf(v4.z); Vs[o+3] = f2tf(v4.w);
        }
        __syncthreads();

        // S = Q^T K : [16q][64k]
        float sacc[8][4];
        #pragma unroll
        for (int nt = 0; nt < 8; nt++)
            #pragma unroll
            for (int j = 0; j < 4; j++) sacc[nt][j] = 0.f;
        #pragma unroll
        for (int kk = 0; kk < 8; kk++) {
            #pragma unroll
            for (int nt = 0; nt < 8; nt++) {
                uint32_t bF[2];
                bF[0] = Ks[(kk * 8 + tig)     * KSTR + nt * 8 + g];
                bF[1] = Ks[(kk * 8 + tig + 4) * KSTR + nt * 8 + g];
                mma_tf32(sacc[nt], aQ[kk], bF);
            }
        }

        // online softmax (rows g and g+8 of this warp's 16-q tile)
        float rmax0 = -1e30f, rmax1 = -1e30f;
        #pragma unroll
        for (int nt = 0; nt < 8; nt++) {
            rmax0 = fmaxf(rmax0, fmaxf(sacc[nt][0], sacc[nt][1]));
            rmax1 = fmaxf(rmax1, fmaxf(sacc[nt][2], sacc[nt][3]));
        }
        #pragma unroll
        for (int o = 1; o <= 2; o <<= 1) {
            rmax0 = fmaxf(rmax0, __shfl_xor_sync(0xffffffffu, rmax0, o));
            rmax1 = fmaxf(rmax1, __shfl_xor_sync(0xffffffffu, rmax1, o));
        }
        float mn0 = fmaxf(m0, rmax0), mn1 = fmaxf(m1, rmax1);
        float corr0 = __expf(m0 - mn0), corr1 = __expf(m1 - mn1);
        m0 = mn0; m1 = mn1;

        float rs0 = 0.f, rs1 = 0.f;
        #pragma unroll
        for (int nt = 0; nt < 8; nt++) {
            sacc[nt][0] = __expf(sacc[nt][0] - m0);
            sacc[nt][1] = __expf(sacc[nt][1] - m0);
            sacc[nt][2] = __expf(sacc[nt][2] - m1);
            sacc[nt][3] = __expf(sacc[nt][3] - m1);
            rs0 += sacc[nt][0] + sacc[nt][1];
            rs1 += sacc[nt][2] + sacc[nt][3];
        }
        #pragma unroll
        for (int o = 1; o <= 2; o <<= 1) {
            rs0 += __shfl_xor_sync(0xffffffffu, rs0, o);
            rs1 += __shfl_xor_sync(0xffffffffu, rs1, o);
        }
        l0 = l0 * corr0 + rs0;
        l1 = l1 * corr1 + rs1;
        #pragma unroll
        for (int ct = 0; ct < 8; ct++) {
            oacc[ct][0] *= corr0; oacc[ct][1] *= corr0;
            oacc[ct][2] *= corr1; oacc[ct][3] *= corr1;
        }

        // P -> smem (per-warp rows; D layout -> A layout via round-trip)
        #pragma unroll
        for (int nt = 0; nt < 8; nt++) {
            uint2 p01, p23;
            p01.x = f2tf(sacc[nt][0]); p01.y = f2tf(sacc[nt][1]);
            p23.x = f2tf(sacc[nt][2]); p23.y = f2tf(sacc[nt][3]);
            *(uint2*)&Ps[(ql + g)     * PSTR + nt * 8 + 2 * tig] = p01;
            *(uint2*)&Ps[(ql + g + 8) * PSTR + nt * 8 + 2 * tig] = p23;
        }
        __syncwarp();

        // O += P V^T : [16q][64c]
        #pragma unroll
        for (int kk = 0; kk < 8; kk++) {
            uint32_t aP[4];
            aP[0] = Ps[(ql + g)     * PSTR + kk * 8 + tig];
            aP[1] = Ps[(ql + g + 8) * PSTR + kk * 8 + tig];
            aP[2] = Ps[(ql + g)     * PSTR + kk * 8 + tig + 4];
            aP[3] = Ps[(ql + g + 8) * PSTR + kk * 8 + tig + 4];
            #pragma unroll
            for (int ct = 0; ct < 8; ct++) {
                uint32_t bF[2];
                bF[0] = Vs[(ct * 8 + g) * KSTR + kk * 8 + tig];
                bF[1] = Vs[(ct * 8 + g) * KSTR + kk * 8 + tig + 4];
                mma_tf32(oacc[ct], aP, bF);
            }
        }
    }

    // normalize + write transposed output [t][c]
    float inv0 = 1.f / l0, inv1 = 1.f / l1;
    float* orow0 = g_attnt + ((size_t)b * TDIM + q0 + ql + g)     * CDIM + head * 64;
    float* orow1 = g_attnt + ((size_t)b * TDIM + q0 + ql + g + 8) * CDIM + head * 64;
    #pragma unroll
    for (int ct = 0; ct < 8; ct++) {
        float2 o0, o1;
        o0.x = oacc[ct][0] * inv0; o0.y = oacc[ct][1] * inv0;
        o1.x = oacc[ct][2] * inv1; o1.y = oacc[ct][3] * inv1;
        *(float2*)(orow0 + ct * 8 + 2 * tig) = o0;
        *(float2*)(orow1 + ct * 8 + 2 * tig) = o1;
    }
}

// ===========================================================================
// GroupNorm #2 (no affine) over y = RES_SCALE*xn + h -> d_out
// ===========================================================================
__global__ __launch_bounds__(256) void gn2_kernel(float* __restrict__ out)
{
    __shared__ float sh[16];
    int blk = blockIdx.x;
    int b = blk >> 5, g = blk & 31;
    size_t off = ((size_t)b * CDIM + (size_t)g * 16) * TDIM;
    const float4* xp = (const float4*)(g_xn + off);
    const float4* hp = (const float4*)(g_h + off);
    int tid = threadIdx.x;

    float4 v[16];
    float s = 0.f, s2 = 0.f;
    #pragma unroll
    for (int j = 0; j < 16; j++) {
        float4 a = xp[j * 256 + tid];
        float4 c = hp[j * 256 + tid];
        float4 y;
        y.x = RES_SCALE_ * a.x + c.x;
        y.y = RES_SCALE_ * a.y + c.y;
        y.z = RES_SCALE_ * a.z + c.z;
        y.w = RES_SCALE_ * a.w + c.w;
        v[j] = y;
        s  += y.x + y.y + y.z + y.w;
        s2 += y.x*y.x + y.y*y.y + y.z*y.z + y.w*y.w;
    }
    block_reduce2(s, s2, sh);
    float mean = s * (1.f / 16384.f);
    float var  = s2 * (1.f / 16384.f) - mean * mean;
    float rstd = rsqrtf(var + EPS_);

    float4* op = (float4*)(out + off);
    #pragma unroll
    for (int j = 0; j < 16; j++) {
        float4 y = v[j], o;
        o.x = (y.x - mean) * rstd; o.y = (y.y - mean) * rstd;
        o.z = (y.z - mean) * rstd; o.w = (y.w - mean) * rstd;
        op[j * 256 + tid] = o;
    }
}

// ===========================================================================
extern "C" void kernel_launch(void* const* d_in, const int* in_sizes, int n_in,
                              void* d_out, int out_size)
{
    const float* x      = (const float*)d_in[0];
    const float* gn_w   = (const float*)d_in[1];
    const float* gn_b   = (const float*)d_in[2];
    const float* qkv_w  = (const float*)d_in[3];
    const float* qkv_b  = (const float*)d_in[4];
    const float* proj_w = (const float*)d_in[5];
    const float* proj_b = (const float*)d_in[6];
    float* out = (float*)d_out;

    cudaFuncSetAttribute(attn_mma_kernel,
                         cudaFuncAttributeMaxDynamicSharedMemorySize, ATTN_SMEM);

    // 1) GroupNorm(affine) -> g_xn [c,t] + g_xnt [t,c]
    gn1_kernel<<<BATCH * 32, 256>>>(x, gn_w, gn_b);

    // 2) QKV GEMM (tf32 mma): [1536,512] x [8][1024,512]^T -> g_qkv [m,t]
    mma_gemm<0><<<dim3(TDIM / 128, 1536 / 128, BATCH), 256>>>(qkv_w, qkv_b);

    // 3) Flash attention (tf32 mma) -> g_attnt [t,c]
    attn_mma_kernel<<<dim3(TDIM / 128, BATCH * HEADS_), 256, ATTN_SMEM>>>();

    // 4) proj GEMM (tf32 mma) -> g_h [c,t]
    mma_gemm<1><<<dim3(TDIM / 128, CDIM / 128, BATCH), 256>>>(proj_w, proj_b);

    // 5) residual + GroupNorm(no affine) -> out
    gn2_kernel<<<BATCH * 32, 256>>>(out);
}

// round 4
// speedup vs baseline: 5.9007x; 1.7518x over previous
#include <cuda_runtime.h>
#include <cuda_bf16.h>
#include <cstdint>
#include <math.h>

// Problem constants
#define BATCH 8
#define CDIM 512
#define TDIM 1024
#define HEADS_ 8
#define EPS_ 1e-5f
#define RES_SCALE_ 0.7071067811865476f
#define QK_SCALE 0.35355339059327373f   // 64^-0.25

// Scratch
__device__ float          g_xn   [BATCH * CDIM * TDIM];       // fp32 residual
__device__ __nv_bfloat16  g_xnt  [BATCH * TDIM * CDIM];       // bf16 [t,c]
__device__ __nv_bfloat16  g_qkvb [BATCH * 3 * CDIM * TDIM];   // bf16 [m,t] (q,v used)
__device__ __nv_bfloat16  g_kt   [BATCH * HEADS_ * TDIM * 64];// bf16 [t,c] per head
__device__ __nv_bfloat16  g_attnt[BATCH * TDIM * CDIM];       // bf16 [t,c]
__device__ float          g_h    [BATCH * CDIM * TDIM];       // fp32

// ===========================================================================
// mma.sync bf16 m16n8k16 (sm_80+ encoding; tcgen05 unavailable on compute_103)
// ===========================================================================
__device__ __forceinline__ void mma_bf16(float* d, const uint32_t* a,
                                         const uint32_t* b) {
    asm volatile(
        "mma.sync.aligned.m16n8k16.row.col.f32.bf16.bf16.f32 "
        "{%0,%1,%2,%3}, {%4,%5,%6,%7}, {%8,%9}, {%0,%1,%2,%3};"
        : "+f"(d[0]), "+f"(d[1]), "+f"(d[2]), "+f"(d[3])
        : "r"(a[0]), "r"(a[1]), "r"(a[2]), "r"(a[3]), "r"(b[0]), "r"(b[1]));
}
__device__ __forceinline__ uint32_t packbf(float lo, float hi) {
    __nv_bfloat162 h = __floats2bfloat162_rn(lo, hi);
    return *(uint32_t*)&h;
}

// ===========================================================================
// Block-wide (256 threads) sum + sumsq reduction
// ===========================================================================
__device__ __forceinline__ void block_reduce2(float& s, float& s2, float* sh)
{
    #pragma unroll
    for (int o = 16; o > 0; o >>= 1) {
        s  += __shfl_down_sync(0xffffffffu, s,  o);
        s2 += __shfl_down_sync(0xffffffffu, s2, o);
    }
    int warp = threadIdx.x >> 5, lane = threadIdx.x & 31;
    if (lane == 0) { sh[warp] = s; sh[8 + warp] = s2; }
    __syncthreads();
    if (threadIdx.x < 32) {
        s  = (lane < 8) ? sh[lane]     : 0.f;
        s2 = (lane < 8) ? sh[8 + lane] : 0.f;
        #pragma unroll
        for (int o = 4; o > 0; o >>= 1) {
            s  += __shfl_down_sync(0xffffffffu, s,  o);
            s2 += __shfl_down_sync(0xffffffffu, s2, o);
        }
        if (lane == 0) { sh[0] = s; sh[1] = s2; }
    }
    __syncthreads();
    s = sh[0]; s2 = sh[1];
}

// ===========================================================================
// GroupNorm #1 (affine): x -> g_xn (fp32 [c,t]) AND g_xnt (bf16 [t,c])
// ===========================================================================
__global__ __launch_bounds__(256) void gn1_kernel(const float* __restrict__ x,
                                                  const float* __restrict__ w,
                                                  const float* __restrict__ bia)
{
    __shared__ float sh[16];
    int blk = blockIdx.x;
    int b = blk >> 5, g = blk & 31;
    size_t off = ((size_t)b * CDIM + (size_t)g * 16) * TDIM;
    const float4* xp = (const float4*)(x + off);
    int tid = threadIdx.x;

    float4 v[16];
    float s = 0.f, s2 = 0.f;
    #pragma unroll
    for (int j = 0; j < 16; j++) {
        float4 a = xp[j * 256 + tid];
        v[j] = a;
        s  += a.x + a.y + a.z + a.w;
        s2 += a.x*a.x + a.y*a.y + a.z*a.z + a.w*a.w;
    }
    block_reduce2(s, s2, sh);
    float mean = s * (1.f / 16384.f);
    float var  = s2 * (1.f / 16384.f) - mean * mean;
    float rstd = rsqrtf(var + EPS_);

    float scl[16], shf[16];
    #pragma unroll
    for (int j = 0; j < 16; j++) {
        int ch = g * 16 + j;
        scl[j] = w[ch] * rstd;
        shf[j] = bia[ch] - mean * scl[j];
    }

    float4* op = (float4*)(g_xn + off);
    #pragma unroll
    for (int j = 0; j < 16; j++) {
        float4 a = v[j], o;
        o.x = a.x * scl[j] + shf[j]; o.y = a.y * scl[j] + shf[j];
        o.z = a.z * scl[j] + shf[j]; o.w = a.w * scl[j] + shf[j];
        v[j] = o;
        op[j * 256 + tid] = o;
    }

    // transposed bf16: xnt[b][t][c]
    __nv_bfloat16* xt = g_xnt + ((size_t)b * TDIM + (size_t)tid * 4) * CDIM + g * 16;
    #pragma unroll
    for (int u = 0; u < 4; u++) {
        uint32_t tmp[8];
        #pragma unroll
        for (int j2 = 0; j2 < 8; j2++)
            tmp[j2] = packbf(((const float*)&v[j2*2])[u],
                             ((const float*)&v[j2*2+1])[u]);
        uint4* r = (uint4*)(xt + (size_t)u * CDIM);
        r[0] = *(uint4*)(tmp);
        r[1] = *(uint4*)(tmp + 4);
    }
}

// ===========================================================================
// bf16 mma GEMM: C[bz][m][t] = W[m][k] * Bt[bz][t][k] + bias[m]
// 128x128 tile, KC=32, 8 warps (4m x 2n), warp tile 32x64, mma m16n8k16.
// MODE 0: Bt=g_xnt,   out -> g_qkvb (q,v) + g_kt (k transposed), bf16
// MODE 1: Bt=g_attnt, out -> g_h fp32
// ===========================================================================
#define KC 32
#define BSTR 40   // bf16 row stride: word stride 20 (== 4 mod 32, odd*4) -> conflict-free

template <int MODE>
__global__ __launch_bounds__(256) void mma_gemm(const float* __restrict__ A,
                                                const float* __restrict__ bias)
{
    __shared__ __nv_bfloat16 As[128 * BSTR];
    __shared__ __nv_bfloat16 Bs[128 * BSTR];
    uint32_t* aw = (uint32_t*)As;
    uint32_t* bw = (uint32_t*)Bs;

    const int tid  = threadIdx.x;
    const int lane = tid & 31;
    const int wrp  = tid >> 5;
    const int g    = lane >> 2, tig = lane & 3;
    const int m0w  = (wrp & 3) * 32;
    const int n0w  = (wrp >> 2) * 64;

    const int z    = blockIdx.z;
    const int row0 = blockIdx.y * 128;
    const int col0 = blockIdx.x * 128;
    const __nv_bfloat16* Bt = (MODE == 0 ? g_xnt : g_attnt) + (size_t)z * TDIM * CDIM;

    const float* Ab = A + (size_t)row0 * CDIM;
    const __nv_bfloat16* Bb = Bt + (size_t)col0 * CDIM;

    float acc[2][8][4];
    #pragma unroll
    for (int mt = 0; mt < 2; mt++)
        #pragma unroll
        for (int nt = 0; nt < 8; nt++)
            #pragma unroll
            for (int j = 0; j < 4; j++) acc[mt][nt][j] = 0.f;

    float4 aR[4];
    uint4  bR[2];
    auto ldg = [&](int k0) {
        #pragma unroll
        for (int s = 0; s < 4; s++) {
            int i = tid + s * 256;
            aR[s] = *(const float4*)(Ab + (size_t)(i >> 3) * CDIM + k0 + (i & 7) * 4);
        }
        #pragma unroll
        for (int s = 0; s < 2; s++) {
            int i = tid + s * 256;
            bR[s] = *(const uint4*)(Bb + (size_t)(i >> 2) * CDIM + k0 + (i & 3) * 8);
        }
    };
    auto sts = [&]() {
        #pragma unroll
        for (int s = 0; s < 4; s++) {
            int i = tid + s * 256;
            uint32_t two[2];
            two[0] = packbf(aR[s].x, aR[s].y);
            two[1] = packbf(aR[s].z, aR[s].w);
            *(uint2*)&As[(i >> 3) * BSTR + (i & 7) * 4] = *(uint2*)two;
        }
        #pragma unroll
        for (int s = 0; s < 2; s++) {
            int i = tid + s * 256;
            *(uint4*)&Bs[(i >> 2) * BSTR + (i & 3) * 8] = bR[s];
        }
    };

    ldg(0);
    #pragma unroll 1
    for (int it = 0; it < CDIM / KC; it++) {
        __syncthreads();
        sts();
        __syncthreads();
        if (it < CDIM / KC - 1) ldg((it + 1) * KC);

        #pragma unroll
        for (int ks = 0; ks < 2; ks++) {
            uint32_t aF[2][4];
            #pragma unroll
            for (int mt = 0; mt < 2; mt++) {
                int r = m0w + mt * 16;
                aF[mt][0] = aw[(r + g)     * 20 + ks * 8 + tig];
                aF[mt][1] = aw[(r + g + 8) * 20 + ks * 8 + tig];
                aF[mt][2] = aw[(r + g)     * 20 + ks * 8 + tig + 4];
                aF[mt][3] = aw[(r + g + 8) * 20 + ks * 8 + tig + 4];
            }
            #pragma unroll
            for (int nt = 0; nt < 8; nt++) {
                uint32_t bF[2];
                int n = n0w + nt * 8 + g;
                bF[0] = bw[n * 20 + ks * 8 + tig];
                bF[1] = bw[n * 20 + ks * 8 + tig + 4];
                mma_bf16(acc[0][nt], aF[0], bF);
                mma_bf16(acc[1][nt], aF[1], bF);
            }
        }
    }

    // Epilogue
    #pragma unroll
    for (int mt = 0; mt < 2; mt++) {
        #pragma unroll
        for (int rr = 0; rr < 2; rr++) {
            int m = row0 + m0w + mt * 16 + g + rr * 8;
            float bv = bias[m];
            if (MODE == 0) {
                int head = m / 192, r = m % 192;
                float scale = (r < 128) ? QK_SCALE : 1.f;
                if (r >= 64 && r < 128) {
                    // K: write transposed g_kt[b][h][t][c]
                    __nv_bfloat16* kb = g_kt + (((size_t)(z * 8 + head)) << 10) * 64 + (r - 64);
                    #pragma unroll
                    for (int nt = 0; nt < 8; nt++) {
                        int t = col0 + n0w + nt * 8 + 2 * tig;
                        float x0 = (acc[mt][nt][rr * 2 + 0] + bv) * scale;
                        float x1 = (acc[mt][nt][rr * 2 + 1] + bv) * scale;
                        kb[(size_t)t * 64]       = __float2bfloat16(x0);
                        kb[(size_t)(t + 1) * 64] = __float2bfloat16(x1);
                    }
                } else {
                    __nv_bfloat16* crow = g_qkvb + ((size_t)z * 1536 + m) * TDIM
                                        + col0 + n0w;
                    #pragma unroll
                    for (int nt = 0; nt < 8; nt++) {
                        uint32_t p = packbf((acc[mt][nt][rr*2+0] + bv) * scale,
                                            (acc[mt][nt][rr*2+1] + bv) * scale);
                        *(uint32_t*)(crow + nt * 8 + 2 * tig) = p;
                    }
                }
            } else {
                float* crow = g_h + ((size_t)z * CDIM + m) * TDIM + col0 + n0w;
                #pragma unroll
                for (int nt = 0; nt < 8; nt++) {
                    float2 o;
                    o.x = acc[mt][nt][rr * 2 + 0] + bv;
                    o.y = acc[mt][nt][rr * 2 + 1] + bv;
                    *(float2*)(crow + nt * 8 + 2 * tig) = o;
                }
            }
        }
    }
}

// ===========================================================================
// Flash attention, bf16 mma m16n8k16. Block = (b,head) x 128 queries, 256 thr.
// Q,V from g_qkvb [m][t]; K from g_kt [t][c]. Output g_attnt bf16 [t][c].
// smem: Ks[64][72] (s-major rows of [s][c]), Vs[64][72] ([c][s]), Ps[128][72]
// ===========================================================================
#define KST 72   // bf16 stride, word stride 36 (== 4 mod 32) -> conflict-free

__global__ __launch_bounds__(256) void attn_mma_kernel()
{
    __shared__ __nv_bfloat16 Ks[64 * KST];
    __shared__ __nv_bfloat16 Vs[64 * KST];
    __shared__ __nv_bfloat16 Ps[128 * KST];
    uint32_t* kw = (uint32_t*)Ks;
    uint32_t* vw = (uint32_t*)Vs;
    uint32_t* pw = (uint32_t*)Ps;

    const int tid  = threadIdx.x;
    const int lane = tid & 31;
    const int wrp  = tid >> 5;
    const int g    = lane >> 2, tig = lane & 3;
    const int ql   = wrp * 16;

    const int bh = blockIdx.y;
    const int b = bh >> 3, head = bh & 7;
    const int q0 = blockIdx.x * 128;

    const __nv_bfloat16* qp  = g_qkvb + ((size_t)b * 1536 + head * 192) * TDIM;
    const __nv_bfloat16* vp  = qp + (size_t)128 * TDIM;
    const __nv_bfloat16* ktp = g_kt + (((size_t)(b * 8 + head)) << 10) * 64;

    // Q fragments (A of S-mma), register-resident
    uint32_t aQ[4][4];
    {
        int tq0 = q0 + ql + g;
        #pragma unroll
        for (int kk = 0; kk < 4; kk++) {
            int c0 = kk * 16 + 2 * tig;
            aQ[kk][0] = packbf(__bfloat162float(qp[(size_t)(c0)     * TDIM + tq0]),
                               __bfloat162float(qp[(size_t)(c0 + 1) * TDIM + tq0]));
            aQ[kk][1] = packbf(__bfloat162float(qp[(size_t)(c0)     * TDIM + tq0 + 8]),
                               __bfloat162float(qp[(size_t)(c0 + 1) * TDIM + tq0 + 8]));
            aQ[kk][2] = packbf(__bfloat162float(qp[(size_t)(c0 + 8) * TDIM + tq0]),
                               __bfloat162float(qp[(size_t)(c0 + 9) * TDIM + tq0]));
            aQ[kk][3] = packbf(__bfloat162float(qp[(size_t)(c0 + 8) * TDIM + tq0 + 8]),
                               __bfloat162float(qp[(size_t)(c0 + 9) * TDIM + tq0 + 8]));
        }
    }

    float oacc[8][4];
    #pragma unroll
    for (int ct = 0; ct < 8; ct++)
        #pragma unroll
        for (int j = 0; j < 4; j++) oacc[ct][j] = 0.f;
    float m0 = -1e30f, m1 = -1e30f, l0 = 0.f, l1 = 0.f;

    #pragma unroll 1
    for (int kt = 0; kt < 16; kt++) {
        const int s0 = kt * 64;
        __syncthreads();
        // Ks[s][c]: straight copy of g_kt rows (coalesced, conflict-free-ish)
        #pragma unroll
        for (int s = 0; s < 2; s++) {
            int i = tid + s * 256;
            int row = i >> 3, ch = i & 7;
            *(uint4*)&Ks[row * KST + ch * 8] =
                *(const uint4*)(ktp + (size_t)(s0 + row) * 64 + ch * 8);
        }
        // Vs[c][s]: copy of v rows
        #pragma unroll
        for (int s = 0; s < 2; s++) {
            int i = tid + s * 256;
            int row = i >> 3, ch = i & 7;
            *(uint4*)&Vs[row * KST + ch * 8] =
                *(const uint4*)(vp + (size_t)row * TDIM + s0 + ch * 8);
        }
        __syncthreads();

        // S = Q^T K : [16q][64s], k-dim = c (4 ksteps of 16)
        float sacc[8][4];
        #pragma unroll
        for (int nt = 0; nt < 8; nt++)
            #pragma unroll
            for (int j = 0; j < 4; j++) sacc[nt][j] = 0.f;
        #pragma unroll
        for (int kk = 0; kk < 4; kk++) {
            #pragma unroll
            for (int nt = 0; nt < 8; nt++) {
                uint32_t bF[2];
                int n = nt * 8 + g;
                bF[0] = kw[n * 36 + kk * 8 + tig];
                bF[1] = kw[n * 36 + kk * 8 + tig + 4];
                mma_bf16(sacc[nt], aQ[kk], bF);
            }
        }

        // online softmax
        float rmax0 = -1e30f, rmax1 = -1e30f;
        #pragma unroll
        for (int nt = 0; nt < 8; nt++) {
            rmax0 = fmaxf(rmax0, fmaxf(sacc[nt][0], sacc[nt][1]));
            rmax1 = fmaxf(rmax1, fmaxf(sacc[nt][2], sacc[nt][3]));
        }
        #pragma unroll
        for (int o = 1; o <= 2; o <<= 1) {
            rmax0 = fmaxf(rmax0, __shfl_xor_sync(0xffffffffu, rmax0, o));
            rmax1 = fmaxf(rmax1, __shfl_xor_sync(0xffffffffu, rmax1, o));
        }
        float mn0 = fmaxf(m0, rmax0), mn1 = fmaxf(m1, rmax1);
        float corr0 = __expf(m0 - mn0), corr1 = __expf(m1 - mn1);
        m0 = mn0; m1 = mn1;

        float rs0 = 0.f, rs1 = 0.f;
        #pragma unroll
        for (int nt = 0; nt < 8; nt++) {
            sacc[nt][0] = __expf(sacc[nt][0] - m0);
            sacc[nt][1] = __expf(sacc[nt][1] - m0);
            sacc[nt][2] = __expf(sacc[nt][2] - m1);
            sacc[nt][3] = __expf(sacc[nt][3] - m1);
            rs0 += sacc[nt][0] + sacc[nt][1];
            rs1 += sacc[nt][2] + sacc[nt][3];
        }
        #pragma unroll
        for (int o = 1; o <= 2; o <<= 1) {
            rs0 += __shfl_xor_sync(0xffffffffu, rs0, o);
            rs1 += __shfl_xor_sync(0xffffffffu, rs1, o);
        }
        l0 = l0 * corr0 + rs0;
        l1 = l1 * corr1 + rs1;
        #pragma unroll
        for (int ct = 0; ct < 8; ct++) {
            oacc[ct][0] *= corr0; oacc[ct][1] *= corr0;
            oacc[ct][2] *= corr1; oacc[ct][3] *= corr1;
        }

        // P -> smem bf16 (per-warp rows)
        #pragma unroll
        for (int nt = 0; nt < 8; nt++) {
            pw[(ql + g)     * 36 + nt * 4 + tig] = packbf(sacc[nt][0], sacc[nt][1]);
            pw[(ql + g + 8) * 36 + nt * 4 + tig] = packbf(sacc[nt][2], sacc[nt][3]);
        }
        __syncwarp();

        // O += P V^T : [16q][64c], k-dim = s (4 ksteps of 16)
        #pragma unroll
        for (int kk = 0; kk < 4; kk++) {
            uint32_t aP[4];
            aP[0] = pw[(ql + g)     * 36 + kk * 8 + tig];
            aP[1] = pw[(ql + g + 8) * 36 + kk * 8 + tig];
            aP[2] = pw[(ql + g)     * 36 + kk * 8 + tig + 4];
            aP[3] = pw[(ql + g + 8) * 36 + kk * 8 + tig + 4];
            #pragma unroll
            for (int ct = 0; ct < 8; ct++) {
                uint32_t bF[2];
                int n = ct * 8 + g;
                bF[0] = vw[n * 36 + kk * 8 + tig];
                bF[1] = vw[n * 36 + kk * 8 + tig + 4];
                mma_bf16(oacc[ct], aP, bF);
            }
        }
    }

    // normalize + write bf16 transposed output [t][c]
    float inv0 = 1.f / l0, inv1 = 1.f / l1;
    __nv_bfloat16* orow0 = g_attnt + ((size_t)b * TDIM + q0 + ql + g)     * CDIM + head * 64;
    __nv_bfloat16* orow1 = g_attnt + ((size_t)b * TDIM + q0 + ql + g + 8) * CDIM + head * 64;
    #pragma unroll
    for (int ct = 0; ct < 8; ct++) {
        *(uint32_t*)(orow0 + ct * 8 + 2 * tig) =
            packbf(oacc[ct][0] * inv0, oacc[ct][1] * inv0);
        *(uint32_t*)(orow1 + ct * 8 + 2 * tig) =
            packbf(oacc[ct][2] * inv1, oacc[ct][3] * inv1);
    }
}

// ===========================================================================
// GroupNorm #2 (no affine) over y = RES_SCALE*xn + h -> d_out
// ===========================================================================
__global__ __launch_bounds__(256) void gn2_kernel(float* __restrict__ out)
{
    __shared__ float sh[16];
    int blk = blockIdx.x;
    int b = blk >> 5, g = blk & 31;
    size_t off = ((size_t)b * CDIM + (size_t)g * 16) * TDIM;
    const float4* xp = (const float4*)(g_xn + off);
    const float4* hp = (const float4*)(g_h + off);
    int tid = threadIdx.x;

    float4 v[16];
    float s = 0.f, s2 = 0.f;
    #pragma unroll
    for (int j = 0; j < 16; j++) {
        float4 a = xp[j * 256 + tid];
        float4 c = hp[j * 256 + tid];
        float4 y;
        y.x = RES_SCALE_ * a.x + c.x;
        y.y = RES_SCALE_ * a.y + c.y;
        y.z = RES_SCALE_ * a.z + c.z;
        y.w = RES_SCALE_ * a.w + c.w;
        v[j] = y;
        s  += y.x + y.y + y.z + y.w;
        s2 += y.x*y.x + y.y*y.y + y.z*y.z + y.w*y.w;
    }
    block_reduce2(s, s2, sh);
    float mean = s * (1.f / 16384.f);
    float var  = s2 * (1.f / 16384.f) - mean * mean;
    float rstd = rsqrtf(var + EPS_);

    float4* op = (float4*)(out + off);
    #pragma unroll
    for (int j = 0; j < 16; j++) {
        float4 y = v[j], o;
        o.x = (y.x - mean) * rstd; o.y = (y.y - mean) * rstd;
        o.z = (y.z - mean) * rstd; o.w = (y.w - mean) * rstd;
        op[j * 256 + tid] = o;
    }
}

// ===========================================================================
extern "C" void kernel_launch(void* const* d_in, const int* in_sizes, int n_in,
                              void* d_out, int out_size)
{
    const float* x      = (const float*)d_in[0];
    const float* gn_w   = (const float*)d_in[1];
    const float* gn_b   = (const float*)d_in[2];
    const float* qkv_w  = (const float*)d_in[3];
    const float* qkv_b  = (const float*)d_in[4];
    const float* proj_w = (const float*)d_in[5];
    const float* proj_b = (const float*)d_in[6];
    float* out = (float*)d_out;

    // 1) GroupNorm(affine) -> g_xn fp32 + g_xnt bf16
    gn1_kernel<<<BATCH * 32, 256>>>(x, gn_w, gn_b);

    // 2) QKV GEMM (bf16 mma) -> g_qkvb (q,v) + g_kt (k transposed)
    mma_gemm<0><<<dim3(TDIM / 128, 1536 / 128, BATCH), 256>>>(qkv_w, qkv_b);

    // 3) Flash attention (bf16 mma) -> g_attnt bf16 [t,c]
    attn_mma_kernel<<<dim3(TDIM / 128, BATCH * HEADS_), 256>>>();

    // 4) proj GEMM (bf16 mma) -> g_h fp32
    mma_gemm<1><<<dim3(TDIM / 128, CDIM / 128, BATCH), 256>>>(proj_w, proj_b);

    // 5) residual + GroupNorm(no affine) -> out
    gn2_kernel<<<BATCH * 32, 256>>>(out);
}

// round 5
// speedup vs baseline: 6.5322x; 1.1070x over previous
#include <cuda_runtime.h>
#include <cuda_bf16.h>
#include <cstdint>
#include <math.h>

// Problem constants
#define BATCH 8
#define CDIM 512
#define TDIM 1024
#define HEADS_ 8
#define EPS_ 1e-5f
#define RES_SCALE_ 0.7071067811865476f
#define QK_SCALE 0.35355339059327373f   // 64^-0.25

// Scratch
__device__ float          g_xn   [BATCH * CDIM * TDIM];       // fp32 residual
__device__ __nv_bfloat16  g_xnt  [BATCH * TDIM * CDIM];       // bf16 [t,c]
__device__ __nv_bfloat16  g_qkvb [BATCH * 3 * CDIM * TDIM];   // bf16 [m,t] (q,v used)
__device__ __nv_bfloat16  g_kt   [BATCH * HEADS_ * TDIM * 64];// bf16 [t,c] per head
__device__ __nv_bfloat16  g_attnt[BATCH * TDIM * CDIM];       // bf16 [t,c]
__device__ float          g_h    [BATCH * CDIM * TDIM];       // fp32
__device__ __nv_bfloat16  g_wqkv [1536 * CDIM];               // bf16 weights
__device__ __nv_bfloat16  g_wproj[CDIM * CDIM];

// ===========================================================================
// mma.sync bf16 m16n8k16 + cp.async helpers
// ===========================================================================
__device__ __forceinline__ void mma_bf16(float* d, const uint32_t* a,
                                         const uint32_t* b) {
    asm volatile(
        "mma.sync.aligned.m16n8k16.row.col.f32.bf16.bf16.f32 "
        "{%0,%1,%2,%3}, {%4,%5,%6,%7}, {%8,%9}, {%0,%1,%2,%3};"
        : "+f"(d[0]), "+f"(d[1]), "+f"(d[2]), "+f"(d[3])
        : "r"(a[0]), "r"(a[1]), "r"(a[2]), "r"(a[3]), "r"(b[0]), "r"(b[1]));
}
__device__ __forceinline__ uint32_t packbf(float lo, float hi) {
    __nv_bfloat162 h = __floats2bfloat162_rn(lo, hi);
    return *(uint32_t*)&h;
}
__device__ __forceinline__ void cp16(void* smem, const void* gmem) {
    uint32_t s = (uint32_t)__cvta_generic_to_shared(smem);
    asm volatile("cp.async.cg.shared.global [%0], [%1], 16;" :: "r"(s), "l"(gmem));
}
#define CP_COMMIT() asm volatile("cp.async.commit_group;" ::: "memory")
#define CP_WAIT1()  asm volatile("cp.async.wait_group 1;" ::: "memory")

// ===========================================================================
// Weight fp32 -> bf16 conversion (runs once per launch, ~1M elems)
// ===========================================================================
__global__ __launch_bounds__(256) void wconv_kernel(const float* __restrict__ qw,
                                                    const float* __restrict__ pw)
{
    const int NQ = 1536 * CDIM / 4;
    const int NP = CDIM * CDIM / 4;
    int i = blockIdx.x * 256 + threadIdx.x;
    if (i < NQ) {
        float4 v = ((const float4*)qw)[i];
        uint2 o; o.x = packbf(v.x, v.y); o.y = packbf(v.z, v.w);
        ((uint2*)g_wqkv)[i] = o;
    } else if (i < NQ + NP) {
        int j = i - NQ;
        float4 v = ((const float4*)pw)[j];
        uint2 o; o.x = packbf(v.x, v.y); o.y = packbf(v.z, v.w);
        ((uint2*)g_wproj)[j] = o;
    }
}

// ===========================================================================
// Block-wide (256 threads) sum + sumsq reduction
// ===========================================================================
__device__ __forceinline__ void block_reduce2(float& s, float& s2, float* sh)
{
    #pragma unroll
    for (int o = 16; o > 0; o >>= 1) {
        s  += __shfl_down_sync(0xffffffffu, s,  o);
        s2 += __shfl_down_sync(0xffffffffu, s2, o);
    }
    int warp = threadIdx.x >> 5, lane = threadIdx.x & 31;
    if (lane == 0) { sh[warp] = s; sh[8 + warp] = s2; }
    __syncthreads();
    if (threadIdx.x < 32) {
        s  = (lane < 8) ? sh[lane]     : 0.f;
        s2 = (lane < 8) ? sh[8 + lane] : 0.f;
        #pragma unroll
        for (int o = 4; o > 0; o >>= 1) {
            s  += __shfl_down_sync(0xffffffffu, s,  o);
            s2 += __shfl_down_sync(0xffffffffu, s2, o);
        }
        if (lane == 0) { sh[0] = s; sh[1] = s2; }
    }
    __syncthreads();
    s = sh[0]; s2 = sh[1];
}

// ===========================================================================
// GroupNorm #1 (affine): x -> g_xn (fp32 [c,t]) AND g_xnt (bf16 [t,c])
// ===========================================================================
__global__ __launch_bounds__(256) void gn1_kernel(const float* __restrict__ x,
                                                  const float* __restrict__ w,
                                                  const float* __restrict__ bia)
{
    __shared__ float sh[16];
    int blk = blockIdx.x;
    int b = blk >> 5, g = blk & 31;
    size_t off = ((size_t)b * CDIM + (size_t)g * 16) * TDIM;
    const float4* xp = (const float4*)(x + off);
    int tid = threadIdx.x;

    float4 v[16];
    float s = 0.f, s2 = 0.f;
    #pragma unroll
    for (int j = 0; j < 16; j++) {
        float4 a = xp[j * 256 + tid];
        v[j] = a;
        s  += a.x + a.y + a.z + a.w;
        s2 += a.x*a.x + a.y*a.y + a.z*a.z + a.w*a.w;
    }
    block_reduce2(s, s2, sh);
    float mean = s * (1.f / 16384.f);
    float var  = s2 * (1.f / 16384.f) - mean * mean;
    float rstd = rsqrtf(var + EPS_);

    float scl[16], shf[16];
    #pragma unroll
    for (int j = 0; j < 16; j++) {
        int ch = g * 16 + j;
        scl[j] = w[ch] * rstd;
        shf[j] = bia[ch] - mean * scl[j];
    }

    float4* op = (float4*)(g_xn + off);
    #pragma unroll
    for (int j = 0; j < 16; j++) {
        float4 a = v[j], o;
        o.x = a.x * scl[j] + shf[j]; o.y = a.y * scl[j] + shf[j];
        o.z = a.z * scl[j] + shf[j]; o.w = a.w * scl[j] + shf[j];
        v[j] = o;
        op[j * 256 + tid] = o;
    }

    __nv_bfloat16* xt = g_xnt + ((size_t)b * TDIM + (size_t)tid * 4) * CDIM + g * 16;
    #pragma unroll
    for (int u = 0; u < 4; u++) {
        uint32_t tmp[8];
        #pragma unroll
        for (int j2 = 0; j2 < 8; j2++)
            tmp[j2] = packbf(((const float*)&v[j2*2])[u],
                             ((const float*)&v[j2*2+1])[u]);
        uint4* r = (uint4*)(xt + (size_t)u * CDIM);
        r[0] = *(uint4*)(tmp);
        r[1] = *(uint4*)(tmp + 4);
    }
}

// ===========================================================================
// bf16 mma GEMM, 3-stage cp.async pipeline.
// C[bz][m][t] = Wbf[m][k] * Bt[bz][t][k] + bias[m]; 128x128 tile, KC=32.
// MODE 0: Bt=g_xnt,   out -> g_qkvb (q,v) + g_kt (k transposed), bf16
// MODE 1: Bt=g_attnt, out -> g_h fp32
// ===========================================================================
#define KC 32
#define BSTR 40
#define GITER (CDIM / KC)
#define GEMM_SMEM (3 * 128 * BSTR * 2 * 2)   // 61440 B

template <int MODE>
__global__ __launch_bounds__(256, 2) void mma_gemm(const float* __restrict__ bias)
{
    extern __shared__ __nv_bfloat16 smg[];
    __nv_bfloat16* As = smg;                       // 3 stages x 128 x BSTR
    __nv_bfloat16* Bs = smg + 3 * 128 * BSTR;

    const int tid  = threadIdx.x;
    const int lane = tid & 31;
    const int wrp  = tid >> 5;
    const int g    = lane >> 2, tig = lane & 3;
    const int m0w  = (wrp & 3) * 32;
    const int n0w  = (wrp >> 2) * 64;

    const int z    = blockIdx.z;
    const int row0 = blockIdx.y * 128;
    const int col0 = blockIdx.x * 128;
    const __nv_bfloat16* Aw = (MODE == 0 ? g_wqkv : g_wproj) + (size_t)row0 * CDIM;
    const __nv_bfloat16* Bb = (MODE == 0 ? g_xnt : g_attnt)
                            + (size_t)z * TDIM * CDIM + (size_t)col0 * CDIM;

    float acc[2][8][4];
    #pragma unroll
    for (int mt = 0; mt < 2; mt++)
        #pragma unroll
        for (int nt = 0; nt < 8; nt++)
            #pragma unroll
            for (int j = 0; j < 4; j++) acc[mt][nt][j] = 0.f;

    auto load_stage = [&](int st, int k0) {
        __nv_bfloat16* pa = As + st * 128 * BSTR;
        __nv_bfloat16* pb = Bs + st * 128 * BSTR;
        #pragma unroll
        for (int s = 0; s < 2; s++) {
            int i = tid + s * 256;
            int row = i >> 2, kc = (i & 3) * 8;
            cp16(pa + row * BSTR + kc, Aw + (size_t)row * CDIM + k0 + kc);
            cp16(pb + row * BSTR + kc, Bb + (size_t)row * CDIM + k0 + kc);
        }
    };

    load_stage(0, 0);      CP_COMMIT();
    load_stage(1, KC);     CP_COMMIT();

    #pragma unroll 1
    for (int it = 0; it < GITER; it++) {
        int st = it % 3;
        CP_WAIT1();
        __syncthreads();
        if (it + 2 < GITER) load_stage((it + 2) % 3, (it + 2) * KC);
        CP_COMMIT();

        const uint32_t* aw = (const uint32_t*)(As + st * 128 * BSTR);
        const uint32_t* bw = (const uint32_t*)(Bs + st * 128 * BSTR);
        #pragma unroll
        for (int ks = 0; ks < 2; ks++) {
            uint32_t aF[2][4];
            #pragma unroll
            for (int mt = 0; mt < 2; mt++) {
                int r = m0w + mt * 16;
                aF[mt][0] = aw[(r + g)     * 20 + ks * 8 + tig];
                aF[mt][1] = aw[(r + g + 8) * 20 + ks * 8 + tig];
                aF[mt][2] = aw[(r + g)     * 20 + ks * 8 + tig + 4];
                aF[mt][3] = aw[(r + g + 8) * 20 + ks * 8 + tig + 4];
            }
            #pragma unroll
            for (int nt = 0; nt < 8; nt++) {
                uint32_t bF[2];
                int n = n0w + nt * 8 + g;
                bF[0] = bw[n * 20 + ks * 8 + tig];
                bF[1] = bw[n * 20 + ks * 8 + tig + 4];
                mma_bf16(acc[0][nt], aF[0], bF);
                mma_bf16(acc[1][nt], aF[1], bF);
            }
        }
    }

    // Epilogue
    #pragma unroll
    for (int mt = 0; mt < 2; mt++) {
        #pragma unroll
        for (int rr = 0; rr < 2; rr++) {
            int m = row0 + m0w + mt * 16 + g + rr * 8;
            float bv = bias[m];
            if (MODE == 0) {
                int head = m / 192, r = m % 192;
                float scale = (r < 128) ? QK_SCALE : 1.f;
                if (r >= 64 && r < 128) {
                    __nv_bfloat16* kb = g_kt + (((size_t)(z * 8 + head)) << 10) * 64 + (r - 64);
                    #pragma unroll
                    for (int nt = 0; nt < 8; nt++) {
                        int t = col0 + n0w + nt * 8 + 2 * tig;
                        float x0 = (acc[mt][nt][rr * 2 + 0] + bv) * scale;
                        float x1 = (acc[mt][nt][rr * 2 + 1] + bv) * scale;
                        kb[(size_t)t * 64]       = __float2bfloat16(x0);
                        kb[(size_t)(t + 1) * 64] = __float2bfloat16(x1);
                    }
                } else {
                    __nv_bfloat16* crow = g_qkvb + ((size_t)z * 1536 + m) * TDIM
                                        + col0 + n0w;
                    #pragma unroll
                    for (int nt = 0; nt < 8; nt++) {
                        uint32_t p = packbf((acc[mt][nt][rr*2+0] + bv) * scale,
                                            (acc[mt][nt][rr*2+1] + bv) * scale);
                        *(uint32_t*)(crow + nt * 8 + 2 * tig) = p;
                    }
                }
            } else {
                float* crow = g_h + ((size_t)z * CDIM + m) * TDIM + col0 + n0w;
                #pragma unroll
                for (int nt = 0; nt < 8; nt++) {
                    float2 o;
                    o.x = acc[mt][nt][rr * 2 + 0] + bv;
                    o.y = acc[mt][nt][rr * 2 + 1] + bv;
                    *(float2*)(crow + nt * 8 + 2 * tig) = o;
                }
            }
        }
    }
}

// ===========================================================================
// Flash attention, bf16 mma, 3-stage cp.async K/V pipeline.
// Block = (b,head) x 128 queries, 256 thr, warp owns 16 queries.
// ===========================================================================
#define KST 72
#define KVSTAGE (64 * KST)
#define ATTN_SMEM ((3 * KVSTAGE * 2 + 128 * KST) * 2)   // 73728 B

__global__ __launch_bounds__(256, 2) void attn_mma_kernel()
{
    extern __shared__ __nv_bfloat16 sma[];
    __nv_bfloat16* Ks = sma;                    // 3 stages
    __nv_bfloat16* Vs = sma + 3 * KVSTAGE;      // 3 stages
    __nv_bfloat16* Ps = sma + 6 * KVSTAGE;
    uint32_t* pw = (uint32_t*)Ps;

    const int tid  = threadIdx.x;
    const int lane = tid & 31;
    const int wrp  = tid >> 5;
    const int g    = lane >> 2, tig = lane & 3;
    const int ql   = wrp * 16;

    const int bh = blockIdx.y;
    const int b = bh >> 3, head = bh & 7;
    const int q0 = blockIdx.x * 128;

    const __nv_bfloat16* qp  = g_qkvb + ((size_t)b * 1536 + head * 192) * TDIM;
    const __nv_bfloat16* vp  = qp + (size_t)128 * TDIM;
    const __nv_bfloat16* ktp = g_kt + (((size_t)(b * 8 + head)) << 10) * 64;

    auto load_stage = [&](int st, int s0) {
        __nv_bfloat16* pk = Ks + st * KVSTAGE;
        __nv_bfloat16* pv = Vs + st * KVSTAGE;
        #pragma unroll
        for (int s = 0; s < 2; s++) {
            int i = tid + s * 256;
            int row = i >> 3, ch8 = (i & 7) * 8;
            cp16(pk + row * KST + ch8, ktp + (size_t)(s0 + row) * 64 + ch8);
            cp16(pv + row * KST + ch8, vp + (size_t)row * TDIM + s0 + ch8);
        }
    };

    // Q fragments, register-resident
    uint32_t aQ[4][4];
    {
        int tq0 = q0 + ql + g;
        #pragma unroll
        for (int kk = 0; kk < 4; kk++) {
            int c0 = kk * 16 + 2 * tig;
            aQ[kk][0] = packbf(__bfloat162float(qp[(size_t)(c0)     * TDIM + tq0]),
                               __bfloat162float(qp[(size_t)(c0 + 1) * TDIM + tq0]));
            aQ[kk][1] = packbf(__bfloat162float(qp[(size_t)(c0)     * TDIM + tq0 + 8]),
                               __bfloat162float(qp[(size_t)(c0 + 1) * TDIM + tq0 + 8]));
            aQ[kk][2] = packbf(__bfloat162float(qp[(size_t)(c0 + 8) * TDIM + tq0]),
                               __bfloat162float(qp[(size_t)(c0 + 9) * TDIM + tq0]));
            aQ[kk][3] = packbf(__bfloat162float(qp[(size_t)(c0 + 8) * TDIM + tq0 + 8]),
                               __bfloat162float(qp[(size_t)(c0 + 9) * TDIM + tq0 + 8]));
        }
    }

    load_stage(0, 0);   CP_COMMIT();
    load_stage(1, 64);  CP_COMMIT();

    float oacc[8][4];
    #pragma unroll
    for (int ct = 0; ct < 8; ct++)
        #pragma unroll
        for (int j = 0; j < 4; j++) oacc[ct][j] = 0.f;
    float m0 = -1e30f, m1 = -1e30f, l0 = 0.f, l1 = 0.f;

    #pragma unroll 1
    for (int kt = 0; kt < 16; kt++) {
        int st = kt % 3;
        CP_WAIT1();
        __syncthreads();
        if (kt + 2 < 16) load_stage((kt + 2) % 3, (kt + 2) * 64);
        CP_COMMIT();

        const uint32_t* kw = (const uint32_t*)(Ks + st * KVSTAGE);
        const uint32_t* vw = (const uint32_t*)(Vs + st * KVSTAGE);

        // S = Q^T K : [16q][64s]
        float sacc[8][4];
        #pragma unroll
        for (int nt = 0; nt < 8; nt++)
            #pragma unroll
            for (int j = 0; j < 4; j++) sacc[nt][j] = 0.f;
        #pragma unroll
        for (int kk = 0; kk < 4; kk++) {
            #pragma unroll
            for (int nt = 0; nt < 8; nt++) {
                uint32_t bF[2];
                int n = nt * 8 + g;
                bF[0] = kw[n * 36 + kk * 8 + tig];
                bF[1] = kw[n * 36 + kk * 8 + tig + 4];
                mma_bf16(sacc[nt], aQ[kk], bF);
            }
        }

        // online softmax
        float rmax0 = -1e30f, rmax1 = -1e30f;
        #pragma unroll
        for (int nt = 0; nt < 8; nt++) {
            rmax0 = fmaxf(rmax0, fmaxf(sacc[nt][0], sacc[nt][1]));
            rmax1 = fmaxf(rmax1, fmaxf(sacc[nt][2], sacc[nt][3]));
        }
        #pragma unroll
        for (int o = 1; o <= 2; o <<= 1) {
            rmax0 = fmaxf(rmax0, __shfl_xor_sync(0xffffffffu, rmax0, o));
            rmax1 = fmaxf(rmax1, __shfl_xor_sync(0xffffffffu, rmax1, o));
        }
        float mn0 = fmaxf(m0, rmax0), mn1 = fmaxf(m1, rmax1);
        float corr0 = __expf(m0 - mn0), corr1 = __expf(m1 - mn1);
        m0 = mn0; m1 = mn1;

        float rs0 = 0.f, rs1 = 0.f;
        #pragma unroll
        for (int nt = 0; nt < 8; nt++) {
            sacc[nt][0] = __expf(sacc[nt][0] - m0);
            sacc[nt][1] = __expf(sacc[nt][1] - m0);
            sacc[nt][2] = __expf(sacc[nt][2] - m1);
            sacc[nt][3] = __expf(sacc[nt][3] - m1);
            rs0 += sacc[nt][0] + sacc[nt][1];
            rs1 += sacc[nt][2] + sacc[nt][3];
        }
        #pragma unroll
        for (int o = 1; o <= 2; o <<= 1) {
            rs0 += __shfl_xor_sync(0xffffffffu, rs0, o);
            rs1 += __shfl_xor_sync(0xffffffffu, rs1, o);
        }
        l0 = l0 * corr0 + rs0;
        l1 = l1 * corr1 + rs1;
        #pragma unroll
        for (int ct = 0; ct < 8; ct++) {
            oacc[ct][0] *= corr0; oacc[ct][1] *= corr0;
            oacc[ct][2] *= corr1; oacc[ct][3] *= corr1;
        }

        // P -> smem bf16 (per-warp rows)
        #pragma unroll
        for (int nt = 0; nt < 8; nt++) {
            pw[(ql + g)     * 36 + nt * 4 + tig] = packbf(sacc[nt][0], sacc[nt][1]);
            pw[(ql + g + 8) * 36 + nt * 4 + tig] = packbf(sacc[nt][2], sacc[nt][3]);
        }
        __syncwarp();

        // O += P V^T : [16q][64c]
        #pragma unroll
        for (int kk = 0; kk < 4; kk++) {
            uint32_t aP[4];
            aP[0] = pw[(ql + g)     * 36 + kk * 8 + tig];
            aP[1] = pw[(ql + g + 8) * 36 + kk * 8 + tig];
            aP[2] = pw[(ql + g)     * 36 + kk * 8 + tig + 4];
            aP[3] = pw[(ql + g + 8) * 36 + kk * 8 + tig + 4];
            #pragma unroll
            for (int ct = 0; ct < 8; ct++) {
                uint32_t bF[2];
                int n = ct * 8 + g;
                bF[0] = vw[n * 36 + kk * 8 + tig];
                bF[1] = vw[n * 36 + kk * 8 + tig + 4];
                mma_bf16(oacc[ct], aP, bF);
            }
        }
    }

    // normalize + write bf16 transposed output [t][c]
    float inv0 = 1.f / l0, inv1 = 1.f / l1;
    __nv_bfloat16* orow0 = g_attnt + ((size_t)b * TDIM + q0 + ql + g)     * CDIM + head * 64;
    __nv_bfloat16* orow1 = g_attnt + ((size_t)b * TDIM + q0 + ql + g + 8) * CDIM + head * 64;
    #pragma unroll
    for (int ct = 0; ct < 8; ct++) {
        *(uint32_t*)(orow0 + ct * 8 + 2 * tig) =
            packbf(oacc[ct][0] * inv0, oacc[ct][1] * inv0);
        *(uint32_t*)(orow1 + ct * 8 + 2 * tig) =
            packbf(oacc[ct][2] * inv1, oacc[ct][3] * inv1);
    }
}

// ===========================================================================
// GroupNorm #2 (no affine) over y = RES_SCALE*xn + h -> d_out
// ===========================================================================
__global__ __launch_bounds__(256) void gn2_kernel(float* __restrict__ out)
{
    __shared__ float sh[16];
    int blk = blockIdx.x;
    int b = blk >> 5, g = blk & 31;
    size_t off = ((size_t)b * CDIM + (size_t)g * 16) * TDIM;
    const float4* xp = (const float4*)(g_xn + off);
    const float4* hp = (const float4*)(g_h + off);
    int tid = threadIdx.x;

    float4 v[16];
    float s = 0.f, s2 = 0.f;
    #pragma unroll
    for (int j = 0; j < 16; j++) {
        float4 a = xp[j * 256 + tid];
        float4 c = hp[j * 256 + tid];
        float4 y;
        y.x = RES_SCALE_ * a.x + c.x;
        y.y = RES_SCALE_ * a.y + c.y;
        y.z = RES_SCALE_ * a.z + c.z;
        y.w = RES_SCALE_ * a.w + c.w;
        v[j] = y;
        s  += y.x + y.y + y.z + y.w;
        s2 += y.x*y.x + y.y*y.y + y.z*y.z + y.w*y.w;
    }
    block_reduce2(s, s2, sh);
    float mean = s * (1.f / 16384.f);
    float var  = s2 * (1.f / 16384.f) - mean * mean;
    float rstd = rsqrtf(var + EPS_);

    float4* op = (float4*)(out + off);
    #pragma unroll
    for (int j = 0; j < 16; j++) {
        float4 y = v[j], o;
        o.x = (y.x - mean) * rstd; o.y = (y.y - mean) * rstd;
        o.z = (y.z - mean) * rstd; o.w = (y.w - mean) * rstd;
        op[j * 256 + tid] = o;
    }
}

// ===========================================================================
extern "C" void kernel_launch(void* const* d_in, const int* in_sizes, int n_in,
                              void* d_out, int out_size)
{
    const float* x      = (const float*)d_in[0];
    const float* gn_w   = (const float*)d_in[1];
    const float* gn_b   = (const float*)d_in[2];
    const float* qkv_w  = (const float*)d_in[3];
    const float* qkv_b  = (const float*)d_in[4];
    const float* proj_w = (const float*)d_in[5];
    const float* proj_b = (const float*)d_in[6];
    float* out = (float*)d_out;

    cudaFuncSetAttribute(mma_gemm<0>, cudaFuncAttributeMaxDynamicSharedMemorySize, GEMM_SMEM);
    cudaFuncSetAttribute(mma_gemm<1>, cudaFuncAttributeMaxDynamicSharedMemorySize, GEMM_SMEM);
    cudaFuncSetAttribute(attn_mma_kernel, cudaFuncAttributeMaxDynamicSharedMemorySize, ATTN_SMEM);

    // 0) weights -> bf16
    wconv_kernel<<<(1536 * CDIM / 4 + CDIM * CDIM / 4 + 255) / 256, 256>>>(qkv_w, proj_w);

    // 1) GroupNorm(affine) -> g_xn fp32 + g_xnt bf16
    gn1_kernel<<<BATCH * 32, 256>>>(x, gn_w, gn_b);

    // 2) QKV GEMM (bf16 mma, cp.async) -> g_qkvb (q,v) + g_kt
    mma_gemm<0><<<dim3(TDIM / 128, 1536 / 128, BATCH), 256, GEMM_SMEM>>>(qkv_b);

    // 3) Flash attention (bf16 mma, cp.async) -> g_attnt bf16 [t,c]
    attn_mma_kernel<<<dim3(TDIM / 128, BATCH * HEADS_), 256, ATTN_SMEM>>>();

    // 4) proj GEMM (bf16 mma, cp.async) -> g_h fp32
    mma_gemm<1><<<dim3(TDIM / 128, CDIM / 128, BATCH), 256, GEMM_SMEM>>>(proj_b);

    // 5) residual + GroupNorm(no affine) -> out
    gn2_kernel<<<BATCH * 32, 256>>>(out);
}

// round 6
// speedup vs baseline: 7.7553x; 1.1872x over previous
#include <cuda_runtime.h>
#include <cuda_bf16.h>
#include <cstdint>
#include <math.h>

// Problem constants
#define BATCH 8
#define CDIM 512
#define TDIM 1024
#define HEADS_ 8
#define EPS_ 1e-5f
#define RES_SCALE_ 0.7071067811865476f
// 64^-0.25 * sqrt(log2(e))  -> softmax uses exp2 directly
#define QK_SCALE_E 0.4246609001440095f

// Scratch
__device__ float          g_xn   [BATCH * CDIM * TDIM];       // fp32 residual
__device__ __nv_bfloat16  g_xnt  [BATCH * TDIM * CDIM];       // bf16 [t,c]
__device__ __nv_bfloat16  g_qkvb [BATCH * 3 * CDIM * TDIM];   // bf16 [m,t] (q,v used)
__device__ __nv_bfloat16  g_kt   [BATCH * HEADS_ * TDIM * 64];// bf16 [t,c] per head
__device__ __nv_bfloat16  g_attnt[BATCH * TDIM * CDIM];       // bf16 [t,c]
__device__ float          g_h    [BATCH * CDIM * TDIM];       // fp32
__device__ __nv_bfloat16  g_wqkv [1536 * CDIM];               // bf16 weights
__device__ __nv_bfloat16  g_wproj[CDIM * CDIM];

// ===========================================================================
// mma.sync bf16 m16n8k16 / ldmatrix / cp.async helpers
// ===========================================================================
__device__ __forceinline__ void mma_bf16(float* d, const uint32_t* a,
                                         const uint32_t* b) {
    asm volatile(
        "mma.sync.aligned.m16n8k16.row.col.f32.bf16.bf16.f32 "
        "{%0,%1,%2,%3}, {%4,%5,%6,%7}, {%8,%9}, {%0,%1,%2,%3};"
        : "+f"(d[0]), "+f"(d[1]), "+f"(d[2]), "+f"(d[3])
        : "r"(a[0]), "r"(a[1]), "r"(a[2]), "r"(a[3]), "r"(b[0]), "r"(b[1]));
}
__device__ __forceinline__ void ldsm_x4(uint32_t* r, uint32_t addr) {
    asm volatile("ldmatrix.sync.aligned.m8n8.x4.shared.b16 {%0,%1,%2,%3}, [%4];"
        : "=r"(r[0]), "=r"(r[1]), "=r"(r[2]), "=r"(r[3]) : "r"(addr));
}
__device__ __forceinline__ uint32_t packbf(float lo, float hi) {
    __nv_bfloat162 h = __floats2bfloat162_rn(lo, hi);
    return *(uint32_t*)&h;
}
__device__ __forceinline__ float ex2f(float x) {
    float y;
    asm("ex2.approx.ftz.f32 %0, %1;" : "=f"(y) : "f"(x));
    return y;
}
__device__ __forceinline__ void cp16(void* smem, const void* gmem) {
    uint32_t s = (uint32_t)__cvta_generic_to_shared(smem);
    asm volatile("cp.async.cg.shared.global [%0], [%1], 16;" :: "r"(s), "l"(gmem));
}
#define CP_COMMIT() asm volatile("cp.async.commit_group;" ::: "memory")
#define CP_WAIT1()  asm volatile("cp.async.wait_group 1;" ::: "memory")

// ===========================================================================
// Weight fp32 -> bf16 conversion
// ===========================================================================
__global__ __launch_bounds__(256) void wconv_kernel(const float* __restrict__ qw,
                                                    const float* __restrict__ pw)
{
    const int NQ = 1536 * CDIM / 4;
    const int NP = CDIM * CDIM / 4;
    int i = blockIdx.x * 256 + threadIdx.x;
    if (i < NQ) {
        float4 v = ((const float4*)qw)[i];
        uint2 o; o.x = packbf(v.x, v.y); o.y = packbf(v.z, v.w);
        ((uint2*)g_wqkv)[i] = o;
    } else if (i < NQ + NP) {
        int j = i - NQ;
        float4 v = ((const float4*)pw)[j];
        uint2 o; o.x = packbf(v.x, v.y); o.y = packbf(v.z, v.w);
        ((uint2*)g_wproj)[j] = o;
    }
}

// ===========================================================================
// Block-wide (256 threads) sum + sumsq reduction
// ===========================================================================
__device__ __forceinline__ void block_reduce2(float& s, float& s2, float* sh)
{
    #pragma unroll
    for (int o = 16; o > 0; o >>= 1) {
        s  += __shfl_down_sync(0xffffffffu, s,  o);
        s2 += __shfl_down_sync(0xffffffffu, s2, o);
    }
    int warp = threadIdx.x >> 5, lane = threadIdx.x & 31;
    if (lane == 0) { sh[warp] = s; sh[8 + warp] = s2; }
    __syncthreads();
    if (threadIdx.x < 32) {
        s  = (lane < 8) ? sh[lane]     : 0.f;
        s2 = (lane < 8) ? sh[8 + lane] : 0.f;
        #pragma unroll
        for (int o = 4; o > 0; o >>= 1) {
            s  += __shfl_down_sync(0xffffffffu, s,  o);
            s2 += __shfl_down_sync(0xffffffffu, s2, o);
        }
        if (lane == 0) { sh[0] = s; sh[1] = s2; }
    }
    __syncthreads();
    s = sh[0]; s2 = sh[1];
}

// ===========================================================================
// GroupNorm #1 (affine): x -> g_xn (fp32 [c,t]) AND g_xnt (bf16 [t,c])
// ===========================================================================
__global__ __launch_bounds__(256) void gn1_kernel(const float* __restrict__ x,
                                                  const float* __restrict__ w,
                                                  const float* __restrict__ bia)
{
    __shared__ float sh[16];
    int blk = blockIdx.x;
    int b = blk >> 5, g = blk & 31;
    size_t off = ((size_t)b * CDIM + (size_t)g * 16) * TDIM;
    const float4* xp = (const float4*)(x + off);
    int tid = threadIdx.x;

    float4 v[16];
    float s = 0.f, s2 = 0.f;
    #pragma unroll
    for (int j = 0; j < 16; j++) {
        float4 a = xp[j * 256 + tid];
        v[j] = a;
        s  += a.x + a.y + a.z + a.w;
        s2 += a.x*a.x + a.y*a.y + a.z*a.z + a.w*a.w;
    }
    block_reduce2(s, s2, sh);
    float mean = s * (1.f / 16384.f);
    float var  = s2 * (1.f / 16384.f) - mean * mean;
    float rstd = rsqrtf(var + EPS_);

    float scl[16], shf[16];
    #pragma unroll
    for (int j = 0; j < 16; j++) {
        int ch = g * 16 + j;
        scl[j] = w[ch] * rstd;
        shf[j] = bia[ch] - mean * scl[j];
    }

    float4* op = (float4*)(g_xn + off);
    #pragma unroll
    for (int j = 0; j < 16; j++) {
        float4 a = v[j], o;
        o.x = a.x * scl[j] + shf[j]; o.y = a.y * scl[j] + shf[j];
        o.z = a.z * scl[j] + shf[j]; o.w = a.w * scl[j] + shf[j];
        v[j] = o;
        op[j * 256 + tid] = o;
    }

    __nv_bfloat16* xt = g_xnt + ((size_t)b * TDIM + (size_t)tid * 4) * CDIM + g * 16;
    #pragma unroll
    for (int u = 0; u < 4; u++) {
        uint32_t tmp[8];
        #pragma unroll
        for (int j2 = 0; j2 < 8; j2++)
            tmp[j2] = packbf(((const float*)&v[j2*2])[u],
                             ((const float*)&v[j2*2+1])[u]);
        uint4* r = (uint4*)(xt + (size_t)u * CDIM);
        r[0] = *(uint4*)(tmp);
        r[1] = *(uint4*)(tmp + 4);
    }
}

// ===========================================================================
// bf16 mma GEMM, 3-stage cp.async pipeline + ldmatrix fragments.
// MODE 0: Bt=g_xnt,   out -> g_qkvb (q,v) + g_kt (k transposed), bf16
// MODE 1: Bt=g_attnt, out -> g_h fp32
// ===========================================================================
#define KC 32
#define BSTR 40                    // bf16 row stride (80 B)
#define GITER (CDIM / KC)
#define GSTAGE (128 * BSTR)        // elems per stage
#define GEMM_SMEM (3 * GSTAGE * 2 * 2)   // 61440 B

template <int MODE>
__global__ __launch_bounds__(256, 2) void mma_gemm(const float* __restrict__ bias)
{
    extern __shared__ __nv_bfloat16 smg[];
    __nv_bfloat16* As = smg;
    __nv_bfloat16* Bs = smg + 3 * GSTAGE;

    const int tid  = threadIdx.x;
    const int lane = tid & 31;
    const int wrp  = tid >> 5;
    const int g    = lane >> 2, tig = lane & 3;
    const int m0w  = (wrp & 3) * 32;
    const int n0w  = (wrp >> 2) * 64;

    // ldmatrix per-lane row offsets (bytes), row stride 80 B
    const int mat = lane >> 3, rowl = lane & 7;
    const uint32_t roffA = ((mat & 1) * 8 + rowl) * 80 + (mat >> 1) * 16;
    const uint32_t roffB = ((mat >> 1) * 8 + rowl) * 80 + (mat & 1) * 16;
    const uint32_t asB = (uint32_t)__cvta_generic_to_shared(As);
    const uint32_t bsB = (uint32_t)__cvta_generic_to_shared(Bs);

    const int z    = blockIdx.z;
    const int row0 = blockIdx.y * 128;
    const int col0 = blockIdx.x * 128;
    const __nv_bfloat16* Aw = (MODE == 0 ? g_wqkv : g_wproj) + (size_t)row0 * CDIM;
    const __nv_bfloat16* Bb = (MODE == 0 ? g_xnt : g_attnt)
                            + (size_t)z * TDIM * CDIM + (size_t)col0 * CDIM;

    float acc[2][8][4];
    #pragma unroll
    for (int mt = 0; mt < 2; mt++)
        #pragma unroll
        for (int nt = 0; nt < 8; nt++)
            #pragma unroll
            for (int j = 0; j < 4; j++) acc[mt][nt][j] = 0.f;

    auto load_stage = [&](int st, int k0) {
        __nv_bfloat16* pa = As + st * GSTAGE;
        __nv_bfloat16* pb = Bs + st * GSTAGE;
        #pragma unroll
        for (int s = 0; s < 2; s++) {
            int i = tid + s * 256;
            int row = i >> 2, kc = (i & 3) * 8;
            cp16(pa + row * BSTR + kc, Aw + (size_t)row * CDIM + k0 + kc);
            cp16(pb + row * BSTR + kc, Bb + (size_t)row * CDIM + k0 + kc);
        }
    };

    load_stage(0, 0);      CP_COMMIT();
    load_stage(1, KC);     CP_COMMIT();

    #pragma unroll 1
    for (int it = 0; it < GITER; it++) {
        int st = it % 3;
        CP_WAIT1();
        __syncthreads();
        if (it + 2 < GITER) load_stage((it + 2) % 3, (it + 2) * KC);
        CP_COMMIT();

        const uint32_t aSt = asB + st * GSTAGE * 2;
        const uint32_t bSt = bsB + st * GSTAGE * 2;
        #pragma unroll
        for (int ks = 0; ks < 2; ks++) {
            uint32_t aF[2][4];
            ldsm_x4(aF[0], aSt + (uint32_t)(m0w)      * 80 + roffA + ks * 32);
            ldsm_x4(aF[1], aSt + (uint32_t)(m0w + 16) * 80 + roffA + ks * 32);
            #pragma unroll
            for (int p = 0; p < 4; p++) {
                uint32_t bF[4];
                ldsm_x4(bF, bSt + (uint32_t)(n0w + p * 16) * 80 + roffB + ks * 32);
                mma_bf16(acc[0][2*p],   aF[0], bF);
                mma_bf16(acc[0][2*p+1], aF[0], bF + 2);
                mma_bf16(acc[1][2*p],   aF[1], bF);
                mma_bf16(acc[1][2*p+1], aF[1], bF + 2);
            }
        }
    }

    // Epilogue
    #pragma unroll
    for (int mt = 0; mt < 2; mt++) {
        #pragma unroll
        for (int rr = 0; rr < 2; rr++) {
            int m = row0 + m0w + mt * 16 + g + rr * 8;
            float bv = bias[m];
            if (MODE == 0) {
                int head = m / 192, r = m % 192;
                float scale = (r < 128) ? QK_SCALE_E : 1.f;
                if (r >= 64 && r < 128) {
                    __nv_bfloat16* kb = g_kt + (((size_t)(z * 8 + head)) << 10) * 64 + (r - 64);
                    #pragma unroll
                    for (int nt = 0; nt < 8; nt++) {
                        int t = col0 + n0w + nt * 8 + 2 * tig;
                        float x0 = (acc[mt][nt][rr * 2 + 0] + bv) * scale;
                        float x1 = (acc[mt][nt][rr * 2 + 1] + bv) * scale;
                        kb[(size_t)t * 64]       = __float2bfloat16(x0);
                        kb[(size_t)(t + 1) * 64] = __float2bfloat16(x1);
                    }
                } else {
                    __nv_bfloat16* crow = g_qkvb + ((size_t)z * 1536 + m) * TDIM
                                        + col0 + n0w;
                    #pragma unroll
                    for (int nt = 0; nt < 8; nt++) {
                        uint32_t p = packbf((acc[mt][nt][rr*2+0] + bv) * scale,
                                            (acc[mt][nt][rr*2+1] + bv) * scale);
                        *(uint32_t*)(crow + nt * 8 + 2 * tig) = p;
                    }
                }
            } else {
                float* crow = g_h + ((size_t)z * CDIM + m) * TDIM + col0 + n0w;
                #pragma unroll
                for (int nt = 0; nt < 8; nt++) {
                    float2 o;
                    o.x = acc[mt][nt][rr * 2 + 0] + bv;
                    o.y = acc[mt][nt][rr * 2 + 1] + bv;
                    *(float2*)(crow + nt * 8 + 2 * tig) = o;
                }
            }
        }
    }
}

// ===========================================================================
// Flash attention: bf16 mma + ldmatrix + register P-repack (no P smem).
// Block = (b,head) x 128 queries, 256 thr, warp owns 16 queries.
// Softmax in exp2 domain (q,k pre-scaled by 64^-0.25*sqrt(log2 e)).
// ===========================================================================
#define KST 72                      // bf16 row stride (144 B)
#define KVSTAGE (64 * KST)
#define ATTN_SMEM (6 * KVSTAGE * 2) // 55296 B

__global__ __launch_bounds__(256, 2) void attn_mma_kernel()
{
    extern __shared__ __nv_bfloat16 sma[];
    __nv_bfloat16* Ks = sma;                    // 3 stages
    __nv_bfloat16* Vs = sma + 3 * KVSTAGE;      // 3 stages

    const int tid  = threadIdx.x;
    const int lane = tid & 31;
    const int wrp  = tid >> 5;
    const int g    = lane >> 2, tig = lane & 3;
    const int ql   = wrp * 16;

    const int mat = lane >> 3, rowl = lane & 7;
    const uint32_t roff = ((mat >> 1) * 8 + rowl) * (KST * 2) + (mat & 1) * 16;
    const uint32_t ksB = (uint32_t)__cvta_generic_to_shared(Ks);
    const uint32_t vsB = (uint32_t)__cvta_generic_to_shared(Vs);

    const int bh = blockIdx.y;
    const int b = bh >> 3, head = bh & 7;
    const int q0 = blockIdx.x * 128;

    const __nv_bfloat16* qp  = g_qkvb + ((size_t)b * 1536 + head * 192) * TDIM;
    const __nv_bfloat16* vp  = qp + (size_t)128 * TDIM;
    const __nv_bfloat16* ktp = g_kt + (((size_t)(b * 8 + head)) << 10) * 64;

    auto load_stage = [&](int st, int s0) {
        __nv_bfloat16* pk = Ks + st * KVSTAGE;
        __nv_bfloat16* pv = Vs + st * KVSTAGE;
        #pragma unroll
        for (int s = 0; s < 2; s++) {
            int i = tid + s * 256;
            int row = i >> 3, ch8 = (i & 7) * 8;
            cp16(pk + row * KST + ch8, ktp + (size_t)(s0 + row) * 64 + ch8);
            cp16(pv + row * KST + ch8, vp + (size_t)row * TDIM + s0 + ch8);
        }
    };

    // Q fragments, register-resident
    uint32_t aQ[4][4];
    {
        int tq0 = q0 + ql + g;
        #pragma unroll
        for (int kk = 0; kk < 4; kk++) {
            int c0 = kk * 16 + 2 * tig;
            aQ[kk][0] = packbf(__bfloat162float(qp[(size_t)(c0)     * TDIM + tq0]),
                               __bfloat162float(qp[(size_t)(c0 + 1) * TDIM + tq0]));
            aQ[kk][1] = packbf(__bfloat162float(qp[(size_t)(c0)     * TDIM + tq0 + 8]),
                               __bfloat162float(qp[(size_t)(c0 + 1) * TDIM + tq0 + 8]));
            aQ[kk][2] = packbf(__bfloat162float(qp[(size_t)(c0 + 8) * TDIM + tq0]),
                               __bfloat162float(qp[(size_t)(c0 + 9) * TDIM + tq0]));
            aQ[kk][3] = packbf(__bfloat162float(qp[(size_t)(c0 + 8) * TDIM + tq0 + 8]),
                               __bfloat162float(qp[(size_t)(c0 + 9) * TDIM + tq0 + 8]));
        }
    }

    load_stage(0, 0);   CP_COMMIT();
    load_stage(1, 64);  CP_COMMIT();

    float oacc[8][4];
    #pragma unroll
    for (int ct = 0; ct < 8; ct++)
        #pragma unroll
        for (int j = 0; j < 4; j++) oacc[ct][j] = 0.f;
    float m0 = -1e30f, m1 = -1e30f, l0 = 0.f, l1 = 0.f;

    #pragma unroll 1
    for (int kt = 0; kt < 16; kt++) {
        int st = kt % 3;
        CP_WAIT1();
        __syncthreads();
        if (kt + 2 < 16) load_stage((kt + 2) % 3, (kt + 2) * 64);
        CP_COMMIT();

        const uint32_t kSt = ksB + st * KVSTAGE * 2;
        const uint32_t vSt = vsB + st * KVSTAGE * 2;

        // S = Q^T K : [16q][64s] via ldmatrix B-fragments
        float sacc[8][4];
        #pragma unroll
        for (int nt = 0; nt < 8; nt++)
            #pragma unroll
            for (int j = 0; j < 4; j++) sacc[nt][j] = 0.f;
        #pragma unroll
        for (int kk = 0; kk < 4; kk++) {
            #pragma unroll
            for (int p = 0; p < 4; p++) {
                uint32_t bF[4];
                ldsm_x4(bF, kSt + p * (16 * KST * 2) + roff + kk * 32);
                mma_bf16(sacc[2*p],   aQ[kk], bF);
                mma_bf16(sacc[2*p+1], aQ[kk], bF + 2);
            }
        }

        // online softmax (exp2 domain)
        float rmax0 = -1e30f, rmax1 = -1e30f;
        #pragma unroll
        for (int nt = 0; nt < 8; nt++) {
            rmax0 = fmaxf(rmax0, fmaxf(sacc[nt][0], sacc[nt][1]));
            rmax1 = fmaxf(rmax1, fmaxf(sacc[nt][2], sacc[nt][3]));
        }
        #pragma unroll
        for (int o = 1; o <= 2; o <<= 1) {
            rmax0 = fmaxf(rmax0, __shfl_xor_sync(0xffffffffu, rmax0, o));
            rmax1 = fmaxf(rmax1, __shfl_xor_sync(0xffffffffu, rmax1, o));
        }
        float mn0 = fmaxf(m0, rmax0), mn1 = fmaxf(m1, rmax1);
        float corr0 = ex2f(m0 - mn0), corr1 = ex2f(m1 - mn1);
        m0 = mn0; m1 = mn1;

        float rs0 = 0.f, rs1 = 0.f;
        #pragma unroll
        for (int nt = 0; nt < 8; nt++) {
            sacc[nt][0] = ex2f(sacc[nt][0] - m0);
            sacc[nt][1] = ex2f(sacc[nt][1] - m0);
            sacc[nt][2] = ex2f(sacc[nt][2] - m1);
            sacc[nt][3] = ex2f(sacc[nt][3] - m1);
            rs0 += sacc[nt][0] + sacc[nt][1];
            rs1 += sacc[nt][2] + sacc[nt][3];
        }
        #pragma unroll
        for (int o = 1; o <= 2; o <<= 1) {
            rs0 += __shfl_xor_sync(0xffffffffu, rs0, o);
            rs1 += __shfl_xor_sync(0xffffffffu, rs1, o);
        }
        l0 = l0 * corr0 + rs0;
        l1 = l1 * corr1 + rs1;
        #pragma unroll
        for (int ct = 0; ct < 8; ct++) {
            oacc[ct][0] *= corr0; oacc[ct][1] *= corr0;
            oacc[ct][2] *= corr1; oacc[ct][3] *= corr1;
        }

        // O += P V^T, P repacked in registers (C-frag == A-frag layout)
        #pragma unroll
        for (int kk = 0; kk < 4; kk++) {
            uint32_t aP[4];
            aP[0] = packbf(sacc[2*kk][0],   sacc[2*kk][1]);
            aP[1] = packbf(sacc[2*kk][2],   sacc[2*kk][3]);
            aP[2] = packbf(sacc[2*kk+1][0], sacc[2*kk+1][1]);
            aP[3] = packbf(sacc[2*kk+1][2], sacc[2*kk+1][3]);
            #pragma unroll
            for (int p = 0; p < 4; p++) {
                uint32_t bF[4];
                ldsm_x4(bF, vSt + p * (16 * KST * 2) + roff + kk * 32);
                mma_bf16(oacc[2*p],   aP, bF);
                mma_bf16(oacc[2*p+1], aP, bF + 2);
            }
        }
    }

    // normalize + write bf16 transposed output [t][c]
    float inv0 = 1.f / l0, inv1 = 1.f / l1;
    __nv_bfloat16* orow0 = g_attnt + ((size_t)b * TDIM + q0 + ql + g)     * CDIM + head * 64;
    __nv_bfloat16* orow1 = g_attnt + ((size_t)b * TDIM + q0 + ql + g + 8) * CDIM + head * 64;
    #pragma unroll
    for (int ct = 0; ct < 8; ct++) {
        *(uint32_t*)(orow0 + ct * 8 + 2 * tig) =
            packbf(oacc[ct][0] * inv0, oacc[ct][1] * inv0);
        *(uint32_t*)(orow1 + ct * 8 + 2 * tig) =
            packbf(oacc[ct][2] * inv1, oacc[ct][3] * inv1);
    }
}

// ===========================================================================
// GroupNorm #2 (no affine) over y = RES_SCALE*xn + h -> d_out
// ===========================================================================
__global__ __launch_bounds__(256) void gn2_kernel(float* __restrict__ out)
{
    __shared__ float sh[16];
    int blk = blockIdx.x;
    int b = blk >> 5, g = blk & 31;
    size_t off = ((size_t)b * CDIM + (size_t)g * 16) * TDIM;
    const float4* xp = (const float4*)(g_xn + off);
    const float4* hp = (const float4*)(g_h + off);
    int tid = threadIdx.x;

    float4 v[16];
    float s = 0.f, s2 = 0.f;
    #pragma unroll
    for (int j = 0; j < 16; j++) {
        float4 a = xp[j * 256 + tid];
        float4 c = hp[j * 256 + tid];
        float4 y;
        y.x = RES_SCALE_ * a.x + c.x;
        y.y = RES_SCALE_ * a.y + c.y;
        y.z = RES_SCALE_ * a.z + c.z;
        y.w = RES_SCALE_ * a.w + c.w;
        v[j] = y;
        s  += y.x + y.y + y.z + y.w;
        s2 += y.x*y.x + y.y*y.y + y.z*y.z + y.w*y.w;
    }
    block_reduce2(s, s2, sh);
    float mean = s * (1.f / 16384.f);
    float var  = s2 * (1.f / 16384.f) - mean * mean;
    float rstd = rsqrtf(var + EPS_);

    float4* op = (float4*)(out + off);
    #pragma unroll
    for (int j = 0; j < 16; j++) {
        float4 y = v[j], o;
        o.x = (y.x - mean) * rstd; o.y = (y.y - mean) * rstd;
        o.z = (y.z - mean) * rstd; o.w = (y.w - mean) * rstd;
        op[j * 256 + tid] = o;
    }
}

// ===========================================================================
extern "C" void kernel_launch(void* const* d_in, const int* in_sizes, int n_in,
                              void* d_out, int out_size)
{
    const float* x      = (const float*)d_in[0];
    const float* gn_w   = (const float*)d_in[1];
    const float* gn_b   = (const float*)d_in[2];
    const float* qkv_w  = (const float*)d_in[3];
    const float* qkv_b  = (const float*)d_in[4];
    const float* proj_w = (const float*)d_in[5];
    const float* proj_b = (const float*)d_in[6];
    float* out = (float*)d_out;

    cudaFuncSetAttribute(mma_gemm<0>, cudaFuncAttributeMaxDynamicSharedMemorySize, GEMM_SMEM);
    cudaFuncSetAttribute(mma_gemm<1>, cudaFuncAttributeMaxDynamicSharedMemorySize, GEMM_SMEM);
    cudaFuncSetAttribute(attn_mma_kernel, cudaFuncAttributeMaxDynamicSharedMemorySize, ATTN_SMEM);

    // 0) weights -> bf16
    wconv_kernel<<<(1536 * CDIM / 4 + CDIM * CDIM / 4 + 255) / 256, 256>>>(qkv_w, proj_w);

    // 1) GroupNorm(affine) -> g_xn fp32 + g_xnt bf16
    gn1_kernel<<<BATCH * 32, 256>>>(x, gn_w, gn_b);

    // 2) QKV GEMM -> g_qkvb (q,v) + g_kt
    mma_gemm<0><<<dim3(TDIM / 128, 1536 / 128, BATCH), 256, GEMM_SMEM>>>(qkv_b);

    // 3) Flash attention -> g_attnt bf16 [t,c]
    attn_mma_kernel<<<dim3(TDIM / 128, BATCH * HEADS_), 256, ATTN_SMEM>>>();

    // 4) proj GEMM -> g_h fp32
    mma_gemm<1><<<dim3(TDIM / 128, CDIM / 128, BATCH), 256, GEMM_SMEM>>>(proj_b);

    // 5) residual + GroupNorm(no affine) -> out
    gn2_kernel<<<BATCH * 32, 256>>>(out);
}